// round 9
// baseline (speedup 1.0000x reference)
#include <cuda_runtime.h>
#include <cstdint>

#define NN 100000
#define EE 1600000

// ---------------- scratch (device globals: the sanctioned no-alloc workaround) ----
__device__ __align__(256) float g_bufA[(size_t)NN * 128];
__device__ __align__(256) float g_bufB[(size_t)NN * 128];
__device__ __align__(256) float g_bufC[(size_t)NN * 128];
__device__ int   g_cnt[NN];
__device__ int   g_rowptr[NN + 1];
__device__ int   g_cursor[NN];
__device__ int   g_bsums[256];
__device__ int   g_csr[EE];
__device__ float g_inv[NN];
__device__ int   g_is64;   // 1 if edge_index is int64, 0 if int32

// Select a scratch buffer by integer selector (1..3) or use the passed pointer
// (sel==0). No int->pointer casts anywhere; globals referenced by symbol only.
__device__ __forceinline__ const float* pickc(const float* p, int sel) {
    if (sel == 1) return g_bufA;
    if (sel == 2) return g_bufB;
    if (sel == 3) return g_bufC;
    return p;
}
__device__ __forceinline__ float* pickm(float* p, int sel) {
    if (sel == 1) return g_bufA;
    if (sel == 2) return g_bufB;
    if (sel == 3) return g_bufC;
    return p;
}

// Edge accessors robust to int32/int64 edge_index. idx in [0, 2E): flattened
// [2, E] array; src = idx<E, dst = idx>=E.
__device__ __forceinline__ int edge_at(const void* ei, size_t idx) {
    if (g_is64) return (int)((const long long*)ei)[idx];
    return ((const int*)ei)[idx];
}

// ---------------- dtype detection -------------------------------------------------
// If int64 (values < 2^31), every odd 32-bit word is 0. If int32, odd words are
// random node indices; OR over 2048 of them is nonzero with overwhelming prob.
__global__ void k_detect(const int* __restrict__ w) {
    __shared__ int sh[256];
    int t = threadIdx.x;
    int nz = 0;
    for (int i = t; i < 2048; i += 256) nz |= w[2 * i + 1];
    sh[t] = nz;
    __syncthreads();
    for (int off = 128; off; off >>= 1) {
        if (t < off) sh[t] |= sh[t + off];
        __syncthreads();
    }
    if (t == 0) g_is64 = (sh[0] == 0) ? 1 : 0;
}

// ---------------- CSR build -------------------------------------------------------
__global__ void k_zero_cnt(int n) {
    int i = blockIdx.x * blockDim.x + threadIdx.x;
    if (i < n) g_cnt[i] = 0;
}

__global__ void k_count(const void* __restrict__ ei, int e) {
    int i = blockIdx.x * blockDim.x + threadIdx.x;
    if (i < e) {
        int d = edge_at(ei, (size_t)e + i);
        if ((unsigned)d < (unsigned)NN) atomicAdd(&g_cnt[d], 1);
    }
}

// per-block (2048 elems) exclusive scan of g_cnt into g_rowptr, block totals to g_bsums
__global__ void k_scan1(int n) {
    __shared__ int sh[256];
    int t = threadIdx.x;
    int base = blockIdx.x * 2048 + t * 8;
    int v[8];
    int s = 0;
#pragma unroll
    for (int r = 0; r < 8; r++) {
        int idx = base + r;
        int c = (idx < n) ? g_cnt[idx] : 0;
        v[r] = s;
        s += c;
    }
    sh[t] = s;
    __syncthreads();
#pragma unroll
    for (int off = 1; off < 256; off <<= 1) {
        int tv = (t >= off) ? sh[t - off] : 0;
        __syncthreads();
        sh[t] += tv;
        __syncthreads();
    }
    if (t == 255) g_bsums[blockIdx.x] = sh[255];
    int excl = t ? sh[t - 1] : 0;
#pragma unroll
    for (int r = 0; r < 8; r++) {
        int idx = base + r;
        if (idx < n) g_rowptr[idx] = excl + v[r];
    }
}

__global__ void k_scan2(int nb) {
    __shared__ int sh[256];
    int t = threadIdx.x;
    int v = (t < nb) ? g_bsums[t] : 0;
    sh[t] = v;
    __syncthreads();
#pragma unroll
    for (int off = 1; off < 256; off <<= 1) {
        int tv = (t >= off) ? sh[t - off] : 0;
        __syncthreads();
        sh[t] += tv;
        __syncthreads();
    }
    if (t < nb) g_bsums[t] = t ? sh[t - 1] : 0;
}

__global__ void k_scan3(int n, int e) {
    int i = blockIdx.x * blockDim.x + threadIdx.x;
    if (i < n) {
        int r = g_rowptr[i] + g_bsums[i >> 11];
        g_rowptr[i] = r;
        g_cursor[i] = r;
        int c = g_cnt[i];
        g_inv[i] = 1.0f / (float)(c > 1 ? c : 1);
    }
    if (i == 0) g_rowptr[n] = e;
}

__global__ void k_scatter(const void* __restrict__ ei, int e) {
    int i = blockIdx.x * blockDim.x + threadIdx.x;
    if (i < e) {
        int d = edge_at(ei, (size_t)e + i);
        int s = edge_at(ei, (size_t)i);
        if ((unsigned)d < (unsigned)NN && (unsigned)s < (unsigned)NN) {
            int p = atomicAdd(&g_cursor[d], 1);
            g_csr[p] = s;
        }
    }
}

// ---------------- mean aggregation over CSR ---------------------------------------
// D/4 lanes cooperate per dst node; each lane owns one float4 column slice.
template <int D>
__global__ void k_agg(const float* Xp, int sX, float* outp, int sO, int n) {
    const float* __restrict__ X = pickc(Xp, sX);
    float* __restrict__ out = pickm(outp, sO);
    constexpr int LPN = D / 4;
    int gid = blockIdx.x * blockDim.x + threadIdx.x;
    int node = gid / LPN;
    int lane = gid % LPN;
    if (node >= n) return;
    int beg = g_rowptr[node];
    int end = g_rowptr[node + 1];
    float4 acc = make_float4(0.f, 0.f, 0.f, 0.f);
    int e = beg;
    for (; e + 1 < end; e += 2) {
        int s0 = g_csr[e];
        int s1 = g_csr[e + 1];
        float4 a = *(const float4*)(X + (size_t)s0 * D + lane * 4);
        float4 b = *(const float4*)(X + (size_t)s1 * D + lane * 4);
        acc.x += a.x + b.x;
        acc.y += a.y + b.y;
        acc.z += a.z + b.z;
        acc.w += a.w + b.w;
    }
    if (e < end) {
        int s0 = g_csr[e];
        float4 a = *(const float4*)(X + (size_t)s0 * D + lane * 4);
        acc.x += a.x;
        acc.y += a.y;
        acc.z += a.z;
        acc.w += a.w;
    }
    float ic = g_inv[node];
    float4 o = make_float4(acc.x * ic, acc.y * ic, acc.z * ic, acc.w * ic);
    *(float4*)(out + (size_t)node * D + lane * 4) = o;
}

// ---------------- fused SAGE GEMM: C = act([W1|W2] . [A1;A2] + b) ------------------
// ACT: 0 = none, 1 = tanh, 2 = leaky(0.01). DUP: also write C2 (mu/logvar).
// BM=128 rows per block, OUT columns covered by 256 threads, 8 cols/thread.
template <int K1, int K2, int OUT, int ACT, bool DUP>
__global__ void __launch_bounds__(256) k_gemm(
    const float* A1p, int sA1, const float* A2p, int sA2,
    const float* __restrict__ W1, const float* __restrict__ W2,
    const float* __restrict__ bias,
    float* Cp, int sC, float* C2p, int n) {
    const float* __restrict__ A1 = pickc(A1p, sA1);
    const float* __restrict__ A2 = pickc(A2p, sA2);
    float* __restrict__ C = pickm(Cp, sC);
    float* __restrict__ C2 = C2p;

    constexpr int KT = K1 + K2;
    constexpr int BM = 128, KC = 16;
    constexpr int TN = OUT / 8;    // 16 (OUT=128) or 8 (OUT=64)
    constexpr int TM = 256 / TN;   // 16 or 32
    constexpr int RM = BM / TM;    // 8 or 4
    constexpr int OUTP = OUT + 1;  // pad against column-stride conflicts

    __shared__ __align__(16) float4 As4[BM][KC / 4 + 1];
    __shared__ float Ws[KC][OUTP];

    int tid = threadIdx.x;
    int tn = tid % TN;
    int tm = tid / TN;
    int row0 = blockIdx.x * BM;

    float acc[RM][8];
#pragma unroll
    for (int i = 0; i < RM; i++)
#pragma unroll
        for (int j = 0; j < 8; j++) acc[i][j] = 0.f;

#pragma unroll 1
    for (int k0 = 0; k0 < KT; k0 += KC) {
        const float* A;
        const float* W;
        int lda, kb;
        if (K1 > 0 && k0 < K1) {
            A = A1; lda = K1; kb = k0; W = W1;
        } else {
            A = A2; lda = K2; kb = k0 - K1; W = W2;
        }
        // A tile: BM x KC = 512 float4, 2 per thread, no transpose
#pragma unroll
        for (int it = 0; it < 2; it++) {
            int f = tid + it * 256;
            int m = f >> 2, kq = f & 3;
            int r = row0 + m;
            float4 v = make_float4(0.f, 0.f, 0.f, 0.f);
            if (r < n) v = *(const float4*)(A + (size_t)r * lda + kb + kq * 4);
            As4[m][kq] = v;
        }
        // W tile: OUT x KC, transposed into Ws[k][o]
#pragma unroll
        for (int it = 0; it < (OUT * 4 + 255) / 256; it++) {
            int f = tid + it * 256;
            if ((OUT * 4) % 256 == 0 || f < OUT * 4) {
                int o = f >> 2, kq = f & 3;
                float4 v = *(const float4*)(W + (size_t)o * lda + kb + kq * 4);
                Ws[kq * 4 + 0][o] = v.x;
                Ws[kq * 4 + 1][o] = v.y;
                Ws[kq * 4 + 2][o] = v.z;
                Ws[kq * 4 + 3][o] = v.w;
            }
        }
        __syncthreads();
#pragma unroll
        for (int kk4 = 0; kk4 < KC / 4; kk4++) {
            float4 a4[RM];
#pragma unroll
            for (int i = 0; i < RM; i++) a4[i] = As4[tm + TM * i][kk4];
#pragma unroll
            for (int q = 0; q < 4; q++) {
                int kk = kk4 * 4 + q;
                float w[8];
#pragma unroll
                for (int j = 0; j < 8; j++) w[j] = Ws[kk][tn + TN * j];
#pragma unroll
                for (int i = 0; i < RM; i++) {
                    float av = (q == 0) ? a4[i].x : (q == 1) ? a4[i].y
                              : (q == 2) ? a4[i].z : a4[i].w;
#pragma unroll
                    for (int j = 0; j < 8; j++) acc[i][j] = fmaf(av, w[j], acc[i][j]);
                }
            }
        }
        __syncthreads();
    }
    // epilogue: bias + activation
#pragma unroll
    for (int i = 0; i < RM; i++) {
        int r = row0 + tm + TM * i;
        if (r < n) {
#pragma unroll
            for (int j = 0; j < 8; j++) {
                int c = tn + TN * j;
                float v = acc[i][j] + bias[c];
                if (ACT == 1) {
                    v = tanhf(v);
                } else if (ACT == 2) {
                    v = v > 0.f ? v : 0.01f * v;
                }
                C[(size_t)r * OUT + c] = v;
                if (DUP) C2[(size_t)r * OUT + c] = v;
            }
        }
    }
}

// ---------------- dec4: OUT=3, warp per node --------------------------------------
__global__ void k_dec4(const float* Amp, int sAm, const float* Op, int sO,
                       const float* __restrict__ Wl, const float* __restrict__ Wr,
                       const float* __restrict__ b,
                       float* __restrict__ out_xy, float* __restrict__ out_z, int n) {
    const float* __restrict__ Am = pickc(Amp, sAm);
    const float* __restrict__ O = pickc(Op, sO);
    int w = (blockIdx.x * blockDim.x + threadIdx.x) >> 5;
    int lane = threadIdx.x & 31;
    if (w >= n) return;
    const float* m = Am + (size_t)w * 64;
    const float* o = O + (size_t)w * 64;
    float m0 = m[lane], m1 = m[lane + 32];
    float o0 = o[lane], o1 = o[lane + 32];
    float r[3];
#pragma unroll
    for (int c = 0; c < 3; c++) {
        float v = Wl[c * 64 + lane] * m0 + Wl[c * 64 + lane + 32] * m1 +
                  Wr[c * 64 + lane] * o0 + Wr[c * 64 + lane + 32] * o1;
#pragma unroll
        for (int s = 16; s; s >>= 1) v += __shfl_down_sync(0xffffffffu, v, s);
        r[c] = v;
    }
    if (lane == 0) {
        out_xy[(size_t)w * 2 + 0] = r[0] + b[0];
        out_xy[(size_t)w * 2 + 1] = r[1] + b[1];
        out_z[w] = r[2] + b[2];
    }
}

// ---------------- host ------------------------------------------------------------
extern "C" void kernel_launch(void* const* d_in, const int* in_sizes, int n_in,
                              void* d_out, int out_size) {
    const float* x = (const float*)d_in[0];
    const void* ei = d_in[1];
    int N = in_sizes[0] / 64;
    int E = in_sizes[1] / 2;

    const float* g1Wl = (const float*)d_in[2];
    const float* g1b  = (const float*)d_in[3];
    const float* g1Wr = (const float*)d_in[4];
    const float* g2Wl = (const float*)d_in[5];
    const float* g2b  = (const float*)d_in[6];
    const float* g2Wr = (const float*)d_in[7];
    const float* g3Wl = (const float*)d_in[8];
    const float* g3b  = (const float*)d_in[9];
    const float* g3Wr = (const float*)d_in[10];
    const float* t2W  = (const float*)d_in[11];
    const float* t2b  = (const float*)d_in[12];
    const float* d1W  = (const float*)d_in[13];
    const float* d1b  = (const float*)d_in[14];
    const float* d2Wl = (const float*)d_in[15];
    const float* d2b  = (const float*)d_in[16];
    const float* d2Wr = (const float*)d_in[17];
    const float* d3Wl = (const float*)d_in[18];
    const float* d3b  = (const float*)d_in[19];
    const float* d3Wr = (const float*)d_in[20];
    const float* d4Wl = (const float*)d_in[21];
    const float* d4b  = (const float*)d_in[22];
    const float* d4Wr = (const float*)d_in[23];

    float* out = (float*)d_out;
    float* out_xy = out;                       // [N,2]
    float* out_z = out + 2 * (size_t)N;        // [N]
    float* mu = out + 3 * (size_t)N;           // [N,64]
    float* logvar = mu + 64 * (size_t)N;       // [N,64]

    // ---- edge dtype detection + CSR build ----
    k_detect<<<1, 256>>>((const int*)ei);
    k_zero_cnt<<<(N + 255) / 256, 256>>>(N);
    k_count<<<(E + 255) / 256, 256>>>(ei, E);
    int NB = (N + 2047) / 2048;
    k_scan1<<<NB, 256>>>(N);
    k_scan2<<<1, 256>>>(NB);
    k_scan3<<<(N + 255) / 256, 256>>>(N, E);
    k_scatter<<<(E + 255) / 256, 256>>>(ei, E);

    int GB = (N + 127) / 128;
    int GA64 = (N * 16 + 255) / 256;
    int GA128 = (N * 32 + 255) / 256;

    // Buffer selectors: 1=A, 2=B, 3=C (0 = use the pointer argument)
    // ---- encoder ----
    k_agg<64><<<GA64, 256>>>(x, 0, nullptr, 1, N);                      // mean(x) -> A
    k_gemm<64, 64, 128, 1, false><<<GB, 256>>>(nullptr, 1, x, 0, g1Wl, g1Wr, g1b, nullptr, 2, nullptr, N);          // h1 -> B
    k_agg<128><<<GA128, 256>>>(nullptr, 2, nullptr, 3, N);              // mean(B) -> C
    k_gemm<128, 128, 128, 1, false><<<GB, 256>>>(nullptr, 3, nullptr, 2, g2Wl, g2Wr, g2b, nullptr, 1, nullptr, N);  // h2 -> A
    k_agg<128><<<GA128, 256>>>(nullptr, 1, nullptr, 3, N);              // mean(A) -> C
    k_gemm<128, 128, 128, 1, false><<<GB, 256>>>(nullptr, 3, nullptr, 1, g3Wl, g3Wr, g3b, nullptr, 2, nullptr, N);  // h3 -> B
    // mu = h3 @ tr2_W.T + b ; logvar = mu (module applies tr2 twice)
    k_gemm<0, 128, 64, 0, true><<<GB, 256>>>(nullptr, 0, nullptr, 2, nullptr, t2W, t2b, mu, 0, logvar, N);

    // ---- decoder ----
    k_gemm<0, 64, 128, 2, false><<<GB, 256>>>(nullptr, 0, mu, 0, nullptr, d1W, d1b, nullptr, 1, nullptr, N);        // o1 -> A
    k_agg<128><<<GA128, 256>>>(nullptr, 1, nullptr, 2, N);              // mean(A) -> B
    k_gemm<128, 128, 128, 2, false><<<GB, 256>>>(nullptr, 2, nullptr, 1, d2Wl, d2Wr, d2b, nullptr, 3, nullptr, N);  // o2 -> C
    k_agg<128><<<GA128, 256>>>(nullptr, 3, nullptr, 2, N);              // mean(C) -> B
    k_gemm<128, 128, 64, 1, false><<<GB, 256>>>(nullptr, 2, nullptr, 3, d3Wl, d3Wr, d3b, nullptr, 1, nullptr, N);   // o3 -> A
    k_agg<64><<<GA64, 256>>>(nullptr, 1, nullptr, 2, N);                // mean(A) -> B
    k_dec4<<<(N * 32 + 255) / 256, 256>>>(nullptr, 2, nullptr, 1, d4Wl, d4Wr, d4b, out_xy, out_z, N);
}

// round 10
// speedup vs baseline: 1.0123x; 1.0123x over previous
#include <cuda_runtime.h>
#include <cstdint>

typedef unsigned long long ull;

#define NN 100000
#define EE 1600000

// ---------------- scratch (device globals: the sanctioned no-alloc workaround) ----
__device__ __align__(256) float g_bufA[(size_t)NN * 128];
__device__ __align__(256) float g_bufB[(size_t)NN * 128];
__device__ __align__(256) float g_bufC[(size_t)NN * 128];
__device__ int   g_cnt[NN];
__device__ int   g_rowptr[NN + 1];
__device__ int   g_cursor[NN];
__device__ int   g_bsums[256];
__device__ int   g_csr[EE];
__device__ float g_inv[NN];
__device__ int   g_is64;   // 1 if edge_index is int64, 0 if int32

// Select a scratch buffer by integer selector (1..3) or use the passed pointer
// (sel==0). Globals referenced by symbol only; no int->pointer casts.
__device__ __forceinline__ const float* pickc(const float* p, int sel) {
    if (sel == 1) return g_bufA;
    if (sel == 2) return g_bufB;
    if (sel == 3) return g_bufC;
    return p;
}
__device__ __forceinline__ float* pickm(float* p, int sel) {
    if (sel == 1) return g_bufA;
    if (sel == 2) return g_bufB;
    if (sel == 3) return g_bufC;
    return p;
}

// ---------------- f32x2 helpers (2x fp32 FFMA throughput on sm_103a) ---------------
__device__ __forceinline__ ull ffma2(ull a, ull b, ull c) {
    ull d;
    asm("fma.rn.f32x2 %0, %1, %2, %3;" : "=l"(d) : "l"(a), "l"(b), "l"(c));
    return d;
}
__device__ __forceinline__ ull pack2(float x) {
    unsigned xi = __float_as_uint(x);
    ull d;
    asm("mov.b64 %0, {%1, %1};" : "=l"(d) : "r"(xi));
    return d;
}
__device__ __forceinline__ float2 unpack2(ull v) {
    unsigned lo, hi;
    asm("mov.b64 {%0, %1}, %2;" : "=r"(lo), "=r"(hi) : "l"(v));
    return make_float2(__uint_as_float(lo), __uint_as_float(hi));
}

// Edge accessors robust to int32/int64 edge_index.
__device__ __forceinline__ int edge_at(const void* ei, size_t idx) {
    if (g_is64) return (int)((const long long*)ei)[idx];
    return ((const int*)ei)[idx];
}

// ---------------- dtype detection -------------------------------------------------
// If int64 (values < 2^31), every odd 32-bit word is 0. If int32, odd words are
// random node indices; OR over 2048 of them is nonzero with overwhelming prob.
__global__ void k_detect(const int* __restrict__ w) {
    __shared__ int sh[256];
    int t = threadIdx.x;
    int nz = 0;
    for (int i = t; i < 2048; i += 256) nz |= w[2 * i + 1];
    sh[t] = nz;
    __syncthreads();
    for (int off = 128; off; off >>= 1) {
        if (t < off) sh[t] |= sh[t + off];
        __syncthreads();
    }
    if (t == 0) g_is64 = (sh[0] == 0) ? 1 : 0;
}

// ---------------- CSR build -------------------------------------------------------
__global__ void k_zero_cnt(int n) {
    int i = blockIdx.x * blockDim.x + threadIdx.x;
    if (i < n) g_cnt[i] = 0;
}

__global__ void k_count(const void* __restrict__ ei, int e) {
    int i = blockIdx.x * blockDim.x + threadIdx.x;
    if (i < e) {
        int d = edge_at(ei, (size_t)e + i);
        if ((unsigned)d < (unsigned)NN) atomicAdd(&g_cnt[d], 1);
    }
}

__global__ void k_scan1(int n) {
    __shared__ int sh[256];
    int t = threadIdx.x;
    int base = blockIdx.x * 2048 + t * 8;
    int v[8];
    int s = 0;
#pragma unroll
    for (int r = 0; r < 8; r++) {
        int idx = base + r;
        int c = (idx < n) ? g_cnt[idx] : 0;
        v[r] = s;
        s += c;
    }
    sh[t] = s;
    __syncthreads();
#pragma unroll
    for (int off = 1; off < 256; off <<= 1) {
        int tv = (t >= off) ? sh[t - off] : 0;
        __syncthreads();
        sh[t] += tv;
        __syncthreads();
    }
    if (t == 255) g_bsums[blockIdx.x] = sh[255];
    int excl = t ? sh[t - 1] : 0;
#pragma unroll
    for (int r = 0; r < 8; r++) {
        int idx = base + r;
        if (idx < n) g_rowptr[idx] = excl + v[r];
    }
}

__global__ void k_scan2(int nb) {
    __shared__ int sh[256];
    int t = threadIdx.x;
    int v = (t < nb) ? g_bsums[t] : 0;
    sh[t] = v;
    __syncthreads();
#pragma unroll
    for (int off = 1; off < 256; off <<= 1) {
        int tv = (t >= off) ? sh[t - off] : 0;
        __syncthreads();
        sh[t] += tv;
        __syncthreads();
    }
    if (t < nb) g_bsums[t] = t ? sh[t - 1] : 0;
}

__global__ void k_scan3(int n, int e) {
    int i = blockIdx.x * blockDim.x + threadIdx.x;
    if (i < n) {
        int r = g_rowptr[i] + g_bsums[i >> 11];
        g_rowptr[i] = r;
        g_cursor[i] = r;
        int c = g_cnt[i];
        g_inv[i] = 1.0f / (float)(c > 1 ? c : 1);
    }
    if (i == 0) g_rowptr[n] = e;
}

__global__ void k_scatter(const void* __restrict__ ei, int e) {
    int i = blockIdx.x * blockDim.x + threadIdx.x;
    if (i < e) {
        int d = edge_at(ei, (size_t)e + i);
        int s = edge_at(ei, (size_t)i);
        if ((unsigned)d < (unsigned)NN && (unsigned)s < (unsigned)NN) {
            int p = atomicAdd(&g_cursor[d], 1);
            g_csr[p] = s;
        }
    }
}

// ---------------- mean aggregation over CSR ---------------------------------------
// D/4 lanes cooperate per dst node; each lane owns one float4 column slice.
template <int D>
__global__ void k_agg(const float* Xp, int sX, float* outp, int sO, int n) {
    const float* __restrict__ X = pickc(Xp, sX);
    float* __restrict__ out = pickm(outp, sO);
    constexpr int LPN = D / 4;
    int gid = blockIdx.x * blockDim.x + threadIdx.x;
    int node = gid / LPN;
    int lane = gid % LPN;
    if (node >= n) return;
    int beg = g_rowptr[node];
    int end = g_rowptr[node + 1];
    float4 acc = make_float4(0.f, 0.f, 0.f, 0.f);
    int e = beg;
    for (; e + 1 < end; e += 2) {
        int s0 = g_csr[e];
        int s1 = g_csr[e + 1];
        float4 a = *(const float4*)(X + (size_t)s0 * D + lane * 4);
        float4 b = *(const float4*)(X + (size_t)s1 * D + lane * 4);
        acc.x += a.x + b.x;
        acc.y += a.y + b.y;
        acc.z += a.z + b.z;
        acc.w += a.w + b.w;
    }
    if (e < end) {
        int s0 = g_csr[e];
        float4 a = *(const float4*)(X + (size_t)s0 * D + lane * 4);
        acc.x += a.x;
        acc.y += a.y;
        acc.z += a.z;
        acc.w += a.w;
    }
    float ic = g_inv[node];
    float4 o = make_float4(acc.x * ic, acc.y * ic, acc.z * ic, acc.w * ic);
    *(float4*)(out + (size_t)node * D + lane * 4) = o;
}

// ---------------- fused SAGE GEMM: C = act([W1|W2] . [A1;A2] + b) ------------------
// ACT: 0 = none, 1 = tanh, 2 = leaky(0.01). DUP: also write C2 (mu/logvar).
// BM=128 rows per block, 256 threads, 8x8 microtile computed as f32x2 pairs via
// fma.rn.f32x2 (2x fp32 throughput on sm_103a).
template <int K1, int K2, int OUT, int ACT, bool DUP>
__global__ void __launch_bounds__(256) k_gemm(
    const float* A1p, int sA1, const float* A2p, int sA2,
    const float* __restrict__ W1, const float* __restrict__ W2,
    const float* __restrict__ bias,
    float* Cp, int sC, float* C2p, int n) {
    const float* __restrict__ A1 = pickc(A1p, sA1);
    const float* __restrict__ A2 = pickc(A2p, sA2);
    float* __restrict__ C = pickm(Cp, sC);
    float* __restrict__ C2 = C2p;

    constexpr int KT = K1 + K2;
    constexpr int BM = 128, KC = 16;
    constexpr int TN = OUT / 8;    // 16 (OUT=128) or 8 (OUT=64)
    constexpr int TM = 256 / TN;   // 16 or 32
    constexpr int RM = BM / TM;    // 8 or 4
    constexpr int OUTP = OUT + 2;  // even pad -> 8B-aligned, conflict-free LDS.64

    __shared__ __align__(16) float4 As4[BM][KC / 4 + 1];
    __shared__ __align__(16) float Ws[KC][OUTP];

    int tid = threadIdx.x;
    int tn = tid % TN;
    int tm = tid / TN;
    int row0 = blockIdx.x * BM;

    ull acc[RM][4];
#pragma unroll
    for (int i = 0; i < RM; i++)
#pragma unroll
        for (int j = 0; j < 4; j++) acc[i][j] = 0ull;

#pragma unroll 1
    for (int k0 = 0; k0 < KT; k0 += KC) {
        const float* A;
        const float* W;
        int lda, kb;
        if (K1 > 0 && k0 < K1) {
            A = A1; lda = K1; kb = k0; W = W1;
        } else {
            A = A2; lda = K2; kb = k0 - K1; W = W2;
        }
        // A tile: BM x KC = 512 float4, 2 per thread, no transpose
#pragma unroll
        for (int it = 0; it < 2; it++) {
            int f = tid + it * 256;
            int m = f >> 2, kq = f & 3;
            int r = row0 + m;
            float4 v = make_float4(0.f, 0.f, 0.f, 0.f);
            if (r < n) v = *(const float4*)(A + (size_t)r * lda + kb + kq * 4);
            As4[m][kq] = v;
        }
        // W tile: OUT x KC, transposed into Ws[k][o]
#pragma unroll
        for (int it = 0; it < (OUT * 4 + 255) / 256; it++) {
            int f = tid + it * 256;
            if ((OUT * 4) % 256 == 0 || f < OUT * 4) {
                int o = f >> 2, kq = f & 3;
                float4 v = *(const float4*)(W + (size_t)o * lda + kb + kq * 4);
                Ws[kq * 4 + 0][o] = v.x;
                Ws[kq * 4 + 1][o] = v.y;
                Ws[kq * 4 + 2][o] = v.z;
                Ws[kq * 4 + 3][o] = v.w;
            }
        }
        __syncthreads();
#pragma unroll
        for (int kk4 = 0; kk4 < KC / 4; kk4++) {
            float4 a4[RM];
#pragma unroll
            for (int i = 0; i < RM; i++) a4[i] = As4[tm + TM * i][kk4];
#pragma unroll
            for (int q = 0; q < 4; q++) {
                int kk = kk4 * 4 + q;
                ull w2[4];
#pragma unroll
                for (int j = 0; j < 4; j++)
                    w2[j] = *(const ull*)&Ws[kk][2 * tn + 2 * TN * j];
#pragma unroll
                for (int i = 0; i < RM; i++) {
                    float av = (q == 0) ? a4[i].x : (q == 1) ? a4[i].y
                              : (q == 2) ? a4[i].z : a4[i].w;
                    ull a2 = pack2(av);
#pragma unroll
                    for (int j = 0; j < 4; j++) acc[i][j] = ffma2(a2, w2[j], acc[i][j]);
                }
            }
        }
        __syncthreads();
    }
    // epilogue: bias + activation
#pragma unroll
    for (int i = 0; i < RM; i++) {
        int r = row0 + tm + TM * i;
        if (r < n) {
#pragma unroll
            for (int j = 0; j < 4; j++) {
                int c = 2 * tn + 2 * TN * j;
                float2 v = unpack2(acc[i][j]);
                v.x += bias[c];
                v.y += bias[c + 1];
                if (ACT == 1) {
                    v.x = tanhf(v.x);
                    v.y = tanhf(v.y);
                } else if (ACT == 2) {
                    v.x = v.x > 0.f ? v.x : 0.01f * v.x;
                    v.y = v.y > 0.f ? v.y : 0.01f * v.y;
                }
                *(float2*)(C + (size_t)r * OUT + c) = v;
                if (DUP) *(float2*)(C2 + (size_t)r * OUT + c) = v;
            }
        }
    }
}

// ---------------- dec4: OUT=3, warp per node --------------------------------------
__global__ void k_dec4(const float* Amp, int sAm, const float* Op, int sO,
                       const float* __restrict__ Wl, const float* __restrict__ Wr,
                       const float* __restrict__ b,
                       float* __restrict__ out_xy, float* __restrict__ out_z, int n) {
    const float* __restrict__ Am = pickc(Amp, sAm);
    const float* __restrict__ O = pickc(Op, sO);
    int w = (blockIdx.x * blockDim.x + threadIdx.x) >> 5;
    int lane = threadIdx.x & 31;
    if (w >= n) return;
    const float* m = Am + (size_t)w * 64;
    const float* o = O + (size_t)w * 64;
    float m0 = m[lane], m1 = m[lane + 32];
    float o0 = o[lane], o1 = o[lane + 32];
    float r[3];
#pragma unroll
    for (int c = 0; c < 3; c++) {
        float v = Wl[c * 64 + lane] * m0 + Wl[c * 64 + lane + 32] * m1 +
                  Wr[c * 64 + lane] * o0 + Wr[c * 64 + lane + 32] * o1;
#pragma unroll
        for (int s = 16; s; s >>= 1) v += __shfl_down_sync(0xffffffffu, v, s);
        r[c] = v;
    }
    if (lane == 0) {
        out_xy[(size_t)w * 2 + 0] = r[0] + b[0];
        out_xy[(size_t)w * 2 + 1] = r[1] + b[1];
        out_z[w] = r[2] + b[2];
    }
}

// ---------------- host ------------------------------------------------------------
extern "C" void kernel_launch(void* const* d_in, const int* in_sizes, int n_in,
                              void* d_out, int out_size) {
    const float* x = (const float*)d_in[0];
    const void* ei = d_in[1];
    int N = in_sizes[0] / 64;
    int E = in_sizes[1] / 2;

    const float* g1Wl = (const float*)d_in[2];
    const float* g1b  = (const float*)d_in[3];
    const float* g1Wr = (const float*)d_in[4];
    const float* g2Wl = (const float*)d_in[5];
    const float* g2b  = (const float*)d_in[6];
    const float* g2Wr = (const float*)d_in[7];
    const float* g3Wl = (const float*)d_in[8];
    const float* g3b  = (const float*)d_in[9];
    const float* g3Wr = (const float*)d_in[10];
    const float* t2W  = (const float*)d_in[11];
    const float* t2b  = (const float*)d_in[12];
    const float* d1W  = (const float*)d_in[13];
    const float* d1b  = (const float*)d_in[14];
    const float* d2Wl = (const float*)d_in[15];
    const float* d2b  = (const float*)d_in[16];
    const float* d2Wr = (const float*)d_in[17];
    const float* d3Wl = (const float*)d_in[18];
    const float* d3b  = (const float*)d_in[19];
    const float* d3Wr = (const float*)d_in[20];
    const float* d4Wl = (const float*)d_in[21];
    const float* d4b  = (const float*)d_in[22];
    const float* d4Wr = (const float*)d_in[23];

    float* out = (float*)d_out;
    float* out_xy = out;                       // [N,2]
    float* out_z = out + 2 * (size_t)N;        // [N]
    float* mu = out + 3 * (size_t)N;           // [N,64]
    float* logvar = mu + 64 * (size_t)N;       // [N,64]

    // ---- edge dtype detection + CSR build ----
    k_detect<<<1, 256>>>((const int*)ei);
    k_zero_cnt<<<(N + 255) / 256, 256>>>(N);
    k_count<<<(E + 255) / 256, 256>>>(ei, E);
    int NB = (N + 2047) / 2048;
    k_scan1<<<NB, 256>>>(N);
    k_scan2<<<1, 256>>>(NB);
    k_scan3<<<(N + 255) / 256, 256>>>(N, E);
    k_scatter<<<(E + 255) / 256, 256>>>(ei, E);

    int GB = (N + 127) / 128;
    int GA64 = (N * 16 + 255) / 256;
    int GA128 = (N * 32 + 255) / 256;

    // Buffer selectors: 1=A, 2=B, 3=C (0 = use the pointer argument)
    // ---- encoder ----
    k_agg<64><<<GA64, 256>>>(x, 0, nullptr, 1, N);                      // mean(x) -> A
    k_gemm<64, 64, 128, 1, false><<<GB, 256>>>(nullptr, 1, x, 0, g1Wl, g1Wr, g1b, nullptr, 2, nullptr, N);          // h1 -> B
    k_agg<128><<<GA128, 256>>>(nullptr, 2, nullptr, 3, N);              // mean(B) -> C
    k_gemm<128, 128, 128, 1, false><<<GB, 256>>>(nullptr, 3, nullptr, 2, g2Wl, g2Wr, g2b, nullptr, 1, nullptr, N);  // h2 -> A
    k_agg<128><<<GA128, 256>>>(nullptr, 1, nullptr, 3, N);              // mean(A) -> C
    k_gemm<128, 128, 128, 1, false><<<GB, 256>>>(nullptr, 3, nullptr, 1, g3Wl, g3Wr, g3b, nullptr, 2, nullptr, N);  // h3 -> B
    // mu = h3 @ tr2_W.T + b ; logvar = mu (module applies tr2 twice)
    k_gemm<0, 128, 64, 0, true><<<GB, 256>>>(nullptr, 0, nullptr, 2, nullptr, t2W, t2b, mu, 0, logvar, N);

    // ---- decoder ----
    k_gemm<0, 64, 128, 2, false><<<GB, 256>>>(nullptr, 0, mu, 0, nullptr, d1W, d1b, nullptr, 1, nullptr, N);        // o1 -> A
    k_agg<128><<<GA128, 256>>>(nullptr, 1, nullptr, 2, N);              // mean(A) -> B
    k_gemm<128, 128, 128, 2, false><<<GB, 256>>>(nullptr, 2, nullptr, 1, d2Wl, d2Wr, d2b, nullptr, 3, nullptr, N);  // o2 -> C
    k_agg<128><<<GA128, 256>>>(nullptr, 3, nullptr, 2, N);              // mean(C) -> B
    k_gemm<128, 128, 64, 1, false><<<GB, 256>>>(nullptr, 2, nullptr, 3, d3Wl, d3Wr, d3b, nullptr, 1, nullptr, N);   // o3 -> A
    k_agg<64><<<GA64, 256>>>(nullptr, 1, nullptr, 2, N);                // mean(A) -> B
    k_dec4<<<(N * 32 + 255) / 256, 256>>>(nullptr, 2, nullptr, 1, d4Wl, d4Wr, d4b, out_xy, out_z, N);
}

// round 14
// speedup vs baseline: 1.6004x; 1.5809x over previous
#include <cuda_runtime.h>
#include <cuda_bf16.h>
#include <cstdint>

#define NN 100000
#define EE 1600000

// ---------------- scratch (device globals: the sanctioned no-alloc workaround) ----
__device__ __align__(256) float g_bufA[(size_t)NN * 128];
__device__ __align__(256) float g_bufB[(size_t)NN * 128];
__device__ __align__(256) float g_bufC[(size_t)NN * 128];
__device__ int   g_cnt[NN];
__device__ int   g_rowptr[NN + 1];
__device__ int   g_cursor[NN];
__device__ int   g_bsums[256];
__device__ int   g_csr[EE];
__device__ float g_inv[NN];
__device__ int   g_is64;

__device__ __forceinline__ const float* pickc(const float* p, int sel) {
    if (sel == 1) return g_bufA;
    if (sel == 2) return g_bufB;
    if (sel == 3) return g_bufC;
    return p;
}
__device__ __forceinline__ float* pickm(float* p, int sel) {
    if (sel == 1) return g_bufA;
    if (sel == 2) return g_bufB;
    if (sel == 3) return g_bufC;
    return p;
}

// ---------------- helpers ----------------------------------------------------------
__device__ __forceinline__ uint32_t smem_u32(const void* p) {
    uint32_t a;
    asm("{ .reg .u64 t; cvta.to.shared.u64 t, %1; cvt.u32.u64 %0, t; }" : "=r"(a) : "l"(p));
    return a;
}
__device__ __forceinline__ uint32_t pack_bf2(float a, float b) {
    __nv_bfloat16 ha = __float2bfloat16(a), hb = __float2bfloat16(b);
    return ((uint32_t)__bfloat16_as_ushort(hb) << 16) | __bfloat16_as_ushort(ha);
}
__device__ __forceinline__ float bf_res(float a) {
    return a - __bfloat162float(__float2bfloat16(a));
}
__device__ __forceinline__ void ldsm4(uint32_t a, uint32_t* r) {
    asm volatile("ldmatrix.sync.aligned.m8n8.x4.shared.b16 {%0,%1,%2,%3}, [%4];"
                 : "=r"(r[0]), "=r"(r[1]), "=r"(r[2]), "=r"(r[3]) : "r"(a));
}
// B from row-major W[n][k] (k contiguous) == col-major k x n: NON-trans ldmatrix.
__device__ __forceinline__ void ldsm2(uint32_t a, uint32_t& b0, uint32_t& b1) {
    asm volatile("ldmatrix.sync.aligned.m8n8.x2.shared.b16 {%0,%1}, [%2];"
                 : "=r"(b0), "=r"(b1) : "r"(a));
}
__device__ __forceinline__ void mmabf(float* d, const uint32_t* a, uint32_t b0, uint32_t b1) {
    asm volatile("mma.sync.aligned.m16n8k16.row.col.f32.bf16.bf16.f32 "
                 "{%0,%1,%2,%3}, {%4,%5,%6,%7}, {%8,%9}, {%0,%1,%2,%3};"
                 : "+f"(d[0]), "+f"(d[1]), "+f"(d[2]), "+f"(d[3])
                 : "r"(a[0]), "r"(a[1]), "r"(a[2]), "r"(a[3]), "r"(b0), "r"(b1));
}

// Edge accessors robust to int32/int64 edge_index.
__device__ __forceinline__ int edge_at(const void* ei, size_t idx) {
    if (g_is64) return (int)((const long long*)ei)[idx];
    return ((const int*)ei)[idx];
}

// ---------------- dtype detection -------------------------------------------------
__global__ void k_detect(const int* __restrict__ w) {
    __shared__ int sh[256];
    int t = threadIdx.x;
    int nz = 0;
    for (int i = t; i < 2048; i += 256) nz |= w[2 * i + 1];
    sh[t] = nz;
    __syncthreads();
    for (int off = 128; off; off >>= 1) {
        if (t < off) sh[t] |= sh[t + off];
        __syncthreads();
    }
    if (t == 0) g_is64 = (sh[0] == 0) ? 1 : 0;
}

// ---------------- CSR build -------------------------------------------------------
__global__ void k_zero_cnt(int n) {
    int i = blockIdx.x * blockDim.x + threadIdx.x;
    if (i < n) g_cnt[i] = 0;
}
__global__ void k_count(const void* __restrict__ ei, int e) {
    int i = blockIdx.x * blockDim.x + threadIdx.x;
    if (i < e) {
        int d = edge_at(ei, (size_t)e + i);
        if ((unsigned)d < (unsigned)NN) atomicAdd(&g_cnt[d], 1);
    }
}
__global__ void k_scan1(int n) {
    __shared__ int sh[256];
    int t = threadIdx.x;
    int base = blockIdx.x * 2048 + t * 8;
    int v[8];
    int s = 0;
#pragma unroll
    for (int r = 0; r < 8; r++) {
        int idx = base + r;
        int c = (idx < n) ? g_cnt[idx] : 0;
        v[r] = s;
        s += c;
    }
    sh[t] = s;
    __syncthreads();
#pragma unroll
    for (int off = 1; off < 256; off <<= 1) {
        int tv = (t >= off) ? sh[t - off] : 0;
        __syncthreads();
        sh[t] += tv;
        __syncthreads();
    }
    if (t == 255) g_bsums[blockIdx.x] = sh[255];
    int excl = t ? sh[t - 1] : 0;
#pragma unroll
    for (int r = 0; r < 8; r++) {
        int idx = base + r;
        if (idx < n) g_rowptr[idx] = excl + v[r];
    }
}
__global__ void k_scan2(int nb) {
    __shared__ int sh[256];
    int t = threadIdx.x;
    int v = (t < nb) ? g_bsums[t] : 0;
    sh[t] = v;
    __syncthreads();
#pragma unroll
    for (int off = 1; off < 256; off <<= 1) {
        int tv = (t >= off) ? sh[t - off] : 0;
        __syncthreads();
        sh[t] += tv;
        __syncthreads();
    }
    if (t < nb) g_bsums[t] = t ? sh[t - 1] : 0;
}
__global__ void k_scan3(int n, int e) {
    int i = blockIdx.x * blockDim.x + threadIdx.x;
    if (i < n) {
        int r = g_rowptr[i] + g_bsums[i >> 11];
        g_rowptr[i] = r;
        g_cursor[i] = r;
        int c = g_cnt[i];
        g_inv[i] = 1.0f / (float)(c > 1 ? c : 1);
    }
    if (i == 0) g_rowptr[n] = e;
}
__global__ void k_scatter(const void* __restrict__ ei, int e) {
    int i = blockIdx.x * blockDim.x + threadIdx.x;
    if (i < e) {
        int d = edge_at(ei, (size_t)e + i);
        int s = edge_at(ei, (size_t)i);
        if ((unsigned)d < (unsigned)NN && (unsigned)s < (unsigned)NN) {
            int p = atomicAdd(&g_cursor[d], 1);
            g_csr[p] = s;
        }
    }
}

// ---------------- mean aggregation over CSR ---------------------------------------
template <int D>
__global__ void k_agg(const float* Xp, int sX, float* outp, int sO, int n) {
    const float* __restrict__ X = pickc(Xp, sX);
    float* __restrict__ out = pickm(outp, sO);
    constexpr int LPN = D / 4;
    int gid = blockIdx.x * blockDim.x + threadIdx.x;
    int node = gid / LPN;
    int lane = gid % LPN;
    if (node >= n) return;
    int beg = g_rowptr[node];
    int end = g_rowptr[node + 1];
    float4 acc = make_float4(0.f, 0.f, 0.f, 0.f);
    int e = beg;
    for (; e + 1 < end; e += 2) {
        int s0 = g_csr[e];
        int s1 = g_csr[e + 1];
        float4 a = *(const float4*)(X + (size_t)s0 * D + lane * 4);
        float4 b = *(const float4*)(X + (size_t)s1 * D + lane * 4);
        acc.x += a.x + b.x;
        acc.y += a.y + b.y;
        acc.z += a.z + b.z;
        acc.w += a.w + b.w;
    }
    if (e < end) {
        int s0 = g_csr[e];
        float4 a = *(const float4*)(X + (size_t)s0 * D + lane * 4);
        acc.x += a.x;
        acc.y += a.y;
        acc.z += a.z;
        acc.w += a.w;
    }
    float ic = g_inv[node];
    float4 o = make_float4(acc.x * ic, acc.y * ic, acc.z * ic, acc.w * ic);
    *(float4*)(out + (size_t)node * D + lane * 4) = o;
}

// ---------------- mma.sync SAGE GEMM: C = act([W1|W2] . [A1;A2] + b) ---------------
// bf16 hi/lo split (3 HMMA terms, fp32 accum) -> ~1e-5 accuracy at tensor-core rate.
// 256 threads = 8 warps x m16 rows = BM 128. K chunked by 32; fp32 -> bf16 hi/lo
// conversion into smem (stride 40 bf16 = 80B, 16B-aligned rows for ldmatrix).
template <int K1, int K2, int OUT, int ACT, bool DUP>
__global__ void __launch_bounds__(256) k_gemm_mma(
    const float* A1p, int sA1, const float* A2p, int sA2,
    const float* __restrict__ W1, const float* __restrict__ W2,
    const float* __restrict__ bias,
    float* Cp, int sC, float* C2p, int n) {
    const float* __restrict__ A1 = pickc(A1p, sA1);
    const float* __restrict__ A2 = pickc(A2p, sA2);
    float* __restrict__ C = pickm(Cp, sC);
    float* __restrict__ C2 = C2p;

    constexpr int KT = K1 + K2;
    constexpr int NT = OUT / 8;       // 16 or 8 n-tiles per warp
    constexpr int STR = 40;           // bf16 row stride (80 bytes)

    __shared__ __align__(16) __nv_bfloat16 Ah[128 * STR];
    __shared__ __align__(16) __nv_bfloat16 Al[128 * STR];
    __shared__ __align__(16) __nv_bfloat16 Wh[OUT * STR];
    __shared__ __align__(16) __nv_bfloat16 Wl[OUT * STR];

    int tid = threadIdx.x;
    int w = tid >> 5;
    int lane = tid & 31;
    int row0 = blockIdx.x * 128;
    int lrow = tid >> 1, half = tid & 1;

    float acc[NT][4];
#pragma unroll
    for (int j = 0; j < NT; j++) {
        acc[j][0] = acc[j][1] = acc[j][2] = acc[j][3] = 0.f;
    }

    uint32_t bAh = smem_u32(Ah), bAl = smem_u32(Al);
    uint32_t bWh = smem_u32(Wh), bWl = smem_u32(Wl);

    // ldmatrix lane->address components (constant across chunks)
    uint32_t aoff = (uint32_t)(w * 16 + (lane & 7) + (lane & 8)) * 80 + ((lane & 16) ? 16u : 0u);
    uint32_t boff = (uint32_t)(lane & 7) * 80 + ((lane & 8) ? 16u : 0u);

#pragma unroll 1
    for (int k0 = 0; k0 < KT; k0 += 32) {
        const float* A;
        const float* W;
        int lda, col0;
        if (K1 > 0 && k0 < K1) { A = A1; W = W1; lda = K1; col0 = k0; }
        else                   { A = A2; W = W2; lda = K2; col0 = k0 - K1; }

        // A tile: 128 rows x 32 cols; thread -> (row = tid/2, 16 cols = tid%2 half)
        {
            int r = row0 + lrow;
            bool val = r < n;
            const float4* src = (const float4*)(A + (size_t)r * lda + col0 + half * 16);
            char* dh = (char*)Ah + lrow * 80 + half * 32;
            char* dl = (char*)Al + lrow * 80 + half * 32;
#pragma unroll
            for (int q = 0; q < 4; q++) {
                float4 v = val ? src[q] : make_float4(0.f, 0.f, 0.f, 0.f);
                uint32_t h0 = pack_bf2(v.x, v.y), h1 = pack_bf2(v.z, v.w);
                uint32_t l0 = pack_bf2(bf_res(v.x), bf_res(v.y));
                uint32_t l1 = pack_bf2(bf_res(v.z), bf_res(v.w));
                *(uint2*)(dh + q * 8) = make_uint2(h0, h1);
                *(uint2*)(dl + q * 8) = make_uint2(l0, l1);
            }
        }
        // W tile: OUT rows x 32 cols
        if (lrow < OUT) {
            const float4* src = (const float4*)(W + (size_t)lrow * lda + col0 + half * 16);
            char* dh = (char*)Wh + lrow * 80 + half * 32;
            char* dl = (char*)Wl + lrow * 80 + half * 32;
#pragma unroll
            for (int q = 0; q < 4; q++) {
                float4 v = src[q];
                uint32_t h0 = pack_bf2(v.x, v.y), h1 = pack_bf2(v.z, v.w);
                uint32_t l0 = pack_bf2(bf_res(v.x), bf_res(v.y));
                uint32_t l1 = pack_bf2(bf_res(v.z), bf_res(v.w));
                *(uint2*)(dh + q * 8) = make_uint2(h0, h1);
                *(uint2*)(dl + q * 8) = make_uint2(l0, l1);
            }
        }
        __syncthreads();

#pragma unroll
        for (int ks = 0; ks < 2; ks++) {
            uint32_t ah[4], al[4];
            ldsm4(bAh + aoff + ks * 32, ah);
            ldsm4(bAl + aoff + ks * 32, al);
#pragma unroll
            for (int j = 0; j < NT; j++) {
                uint32_t ba = (uint32_t)(j * 8) * 80 + boff + ks * 32;
                uint32_t bh0, bh1, bl0, bl1;
                ldsm2(bWh + ba, bh0, bh1);
                ldsm2(bWl + ba, bl0, bl1);
                mmabf(acc[j], ah, bh0, bh1);
                mmabf(acc[j], ah, bl0, bl1);
                mmabf(acc[j], al, bh0, bh1);
            }
        }
        __syncthreads();
    }

    // epilogue: D fragment (r0 = g, r1 = g+8; cols 2*t4, 2*t4+1 per n-tile)
    int g = lane >> 2, t4 = lane & 3;
    int r0 = row0 + w * 16 + g, r1 = r0 + 8;
#pragma unroll
    for (int j = 0; j < NT; j++) {
        int c = j * 8 + t4 * 2;
        float b0 = bias[c], b1 = bias[c + 1];
        float v00 = acc[j][0] + b0, v01 = acc[j][1] + b1;
        float v10 = acc[j][2] + b0, v11 = acc[j][3] + b1;
        if (ACT == 1) {
            v00 = tanhf(v00); v01 = tanhf(v01); v10 = tanhf(v10); v11 = tanhf(v11);
        } else if (ACT == 2) {
            v00 = v00 > 0.f ? v00 : 0.01f * v00;
            v01 = v01 > 0.f ? v01 : 0.01f * v01;
            v10 = v10 > 0.f ? v10 : 0.01f * v10;
            v11 = v11 > 0.f ? v11 : 0.01f * v11;
        }
        if (r0 < n) {
            *(float2*)(C + (size_t)r0 * OUT + c) = make_float2(v00, v01);
            if (DUP) *(float2*)(C2 + (size_t)r0 * OUT + c) = make_float2(v00, v01);
        }
        if (r1 < n) {
            *(float2*)(C + (size_t)r1 * OUT + c) = make_float2(v10, v11);
            if (DUP) *(float2*)(C2 + (size_t)r1 * OUT + c) = make_float2(v10, v11);
        }
    }
}

// ---------------- dec4: OUT=3, warp per node --------------------------------------
__global__ void k_dec4(const float* Amp, int sAm, const float* Op, int sO,
                       const float* __restrict__ Wl, const float* __restrict__ Wr,
                       const float* __restrict__ b,
                       float* __restrict__ out_xy, float* __restrict__ out_z, int n) {
    const float* __restrict__ Am = pickc(Amp, sAm);
    const float* __restrict__ O = pickc(Op, sO);
    int w = (blockIdx.x * blockDim.x + threadIdx.x) >> 5;
    int lane = threadIdx.x & 31;
    if (w >= n) return;
    const float* m = Am + (size_t)w * 64;
    const float* o = O + (size_t)w * 64;
    float m0 = m[lane], m1 = m[lane + 32];
    float o0 = o[lane], o1 = o[lane + 32];
    float r[3];
#pragma unroll
    for (int c = 0; c < 3; c++) {
        float v = Wl[c * 64 + lane] * m0 + Wl[c * 64 + lane + 32] * m1 +
                  Wr[c * 64 + lane] * o0 + Wr[c * 64 + lane + 32] * o1;
#pragma unroll
        for (int s = 16; s; s >>= 1) v += __shfl_down_sync(0xffffffffu, v, s);
        r[c] = v;
    }
    if (lane == 0) {
        out_xy[(size_t)w * 2 + 0] = r[0] + b[0];
        out_xy[(size_t)w * 2 + 1] = r[1] + b[1];
        out_z[w] = r[2] + b[2];
    }
}

// ---------------- host ------------------------------------------------------------
extern "C" void kernel_launch(void* const* d_in, const int* in_sizes, int n_in,
                              void* d_out, int out_size) {
    const float* x = (const float*)d_in[0];
    const void* ei = d_in[1];
    int N = in_sizes[0] / 64;
    int E = in_sizes[1] / 2;

    const float* g1Wl = (const float*)d_in[2];
    const float* g1b  = (const float*)d_in[3];
    const float* g1Wr = (const float*)d_in[4];
    const float* g2Wl = (const float*)d_in[5];
    const float* g2b  = (const float*)d_in[6];
    const float* g2Wr = (const float*)d_in[7];
    const float* g3Wl = (const float*)d_in[8];
    const float* g3b  = (const float*)d_in[9];
    const float* g3Wr = (const float*)d_in[10];
    const float* t2W  = (const float*)d_in[11];
    const float* t2b  = (const float*)d_in[12];
    const float* d1W  = (const float*)d_in[13];
    const float* d1b  = (const float*)d_in[14];
    const float* d2Wl = (const float*)d_in[15];
    const float* d2b  = (const float*)d_in[16];
    const float* d2Wr = (const float*)d_in[17];
    const float* d3Wl = (const float*)d_in[18];
    const float* d3b  = (const float*)d_in[19];
    const float* d3Wr = (const float*)d_in[20];
    const float* d4Wl = (const float*)d_in[21];
    const float* d4b  = (const float*)d_in[22];
    const float* d4Wr = (const float*)d_in[23];

    float* out = (float*)d_out;
    float* out_xy = out;
    float* out_z = out + 2 * (size_t)N;
    float* mu = out + 3 * (size_t)N;
    float* logvar = mu + 64 * (size_t)N;

    // ---- edge dtype detection + CSR build ----
    k_detect<<<1, 256>>>((const int*)ei);
    k_zero_cnt<<<(N + 255) / 256, 256>>>(N);
    k_count<<<(E + 255) / 256, 256>>>(ei, E);
    int NB = (N + 2047) / 2048;
    k_scan1<<<NB, 256>>>(N);
    k_scan2<<<1, 256>>>(NB);
    k_scan3<<<(N + 255) / 256, 256>>>(N, E);
    k_scatter<<<(E + 255) / 256, 256>>>(ei, E);

    int GB = (N + 127) / 128;
    int GA64 = (N * 16 + 255) / 256;
    int GA128 = (N * 32 + 255) / 256;

    // Buffer selectors: 1=A, 2=B, 3=C (0 = use the pointer argument)
    // ---- encoder ----
    k_agg<64><<<GA64, 256>>>(x, 0, nullptr, 1, N);
    k_gemm_mma<64, 64, 128, 1, false><<<GB, 256>>>(nullptr, 1, x, 0, g1Wl, g1Wr, g1b, nullptr, 2, nullptr, N);
    k_agg<128><<<GA128, 256>>>(nullptr, 2, nullptr, 3, N);
    k_gemm_mma<128, 128, 128, 1, false><<<GB, 256>>>(nullptr, 3, nullptr, 2, g2Wl, g2Wr, g2b, nullptr, 1, nullptr, N);
    k_agg<128><<<GA128, 256>>>(nullptr, 1, nullptr, 3, N);
    k_gemm_mma<128, 128, 128, 1, false><<<GB, 256>>>(nullptr, 3, nullptr, 1, g3Wl, g3Wr, g3b, nullptr, 2, nullptr, N);
    // mu = h3 @ tr2_W.T + b ; logvar = mu
    k_gemm_mma<0, 128, 64, 0, true><<<GB, 256>>>(nullptr, 0, nullptr, 2, nullptr, t2W, t2b, mu, 0, logvar, N);

    // ---- decoder ----
    k_gemm_mma<0, 64, 128, 2, false><<<GB, 256>>>(nullptr, 0, mu, 0, nullptr, d1W, d1b, nullptr, 1, nullptr, N);
    k_agg<128><<<GA128, 256>>>(nullptr, 1, nullptr, 2, N);
    k_gemm_mma<128, 128, 128, 2, false><<<GB, 256>>>(nullptr, 2, nullptr, 1, d2Wl, d2Wr, d2b, nullptr, 3, nullptr, N);
    k_agg<128><<<GA128, 256>>>(nullptr, 3, nullptr, 2, N);
    k_gemm_mma<128, 128, 64, 1, false><<<GB, 256>>>(nullptr, 2, nullptr, 3, d3Wl, d3Wr, d3b, nullptr, 1, nullptr, N);
    k_agg<64><<<GA64, 256>>>(nullptr, 1, nullptr, 2, N);
    k_dec4<<<(N * 32 + 255) / 256, 256>>>(nullptr, 2, nullptr, 1, d4Wl, d4Wr, d4b, out_xy, out_z, N);
}

// round 15
// speedup vs baseline: 1.6345x; 1.0213x over previous
#include <cuda_runtime.h>
#include <cuda_bf16.h>
#include <cstdint>

#define NN 100000
#define EE 1600000

// ---------------- scratch (device globals: the sanctioned no-alloc workaround) ----
__device__ __align__(256) float g_bufA[(size_t)NN * 128];
__device__ __align__(256) float g_bufB[(size_t)NN * 128];
__device__ __align__(256) float g_bufC[(size_t)NN * 128];
__device__ int   g_cnt[NN];
__device__ int   g_rowptr[NN + 1];
__device__ int   g_cursor[NN];
__device__ int   g_bsums[256];
__device__ int   g_csr[EE];
__device__ float g_inv[NN];
__device__ int   g_is64;

// Pre-converted weights: 7 layers, slab stride 32768 (max OUT*KT = 128*256).
__device__ __align__(256) __nv_bfloat16 g_wh[7 * 32768];
__device__ __align__(256) __nv_bfloat16 g_wl[7 * 32768];

__device__ __forceinline__ const float* pickc(const float* p, int sel) {
    if (sel == 1) return g_bufA;
    if (sel == 2) return g_bufB;
    if (sel == 3) return g_bufC;
    return p;
}
__device__ __forceinline__ float* pickm(float* p, int sel) {
    if (sel == 1) return g_bufA;
    if (sel == 2) return g_bufB;
    if (sel == 3) return g_bufC;
    return p;
}

// ---------------- helpers ----------------------------------------------------------
__device__ __forceinline__ uint32_t smem_u32(const void* p) {
    uint32_t a;
    asm("{ .reg .u64 t; cvta.to.shared.u64 t, %1; cvt.u32.u64 %0, t; }" : "=r"(a) : "l"(p));
    return a;
}
__device__ __forceinline__ uint32_t pack_bf2(float a, float b) {
    uint32_t r;  // r = bf16(b)<<16 | bf16(a)
    asm("cvt.rn.bf16x2.f32 %0, %1, %2;" : "=r"(r) : "f"(b), "f"(a));
    return r;
}
__device__ __forceinline__ void ldsm4(uint32_t a, uint32_t* r) {
    asm volatile("ldmatrix.sync.aligned.m8n8.x4.shared.b16 {%0,%1,%2,%3}, [%4];"
                 : "=r"(r[0]), "=r"(r[1]), "=r"(r[2]), "=r"(r[3]) : "r"(a));
}
// B from row-major W[n][k] (k contiguous) == col-major k x n: NON-trans ldmatrix.
__device__ __forceinline__ void ldsm2(uint32_t a, uint32_t& b0, uint32_t& b1) {
    asm volatile("ldmatrix.sync.aligned.m8n8.x2.shared.b16 {%0,%1}, [%2];"
                 : "=r"(b0), "=r"(b1) : "r"(a));
}
__device__ __forceinline__ void mmabf(float* d, const uint32_t* a, uint32_t b0, uint32_t b1) {
    asm volatile("mma.sync.aligned.m16n8k16.row.col.f32.bf16.bf16.f32 "
                 "{%0,%1,%2,%3}, {%4,%5,%6,%7}, {%8,%9}, {%0,%1,%2,%3};"
                 : "+f"(d[0]), "+f"(d[1]), "+f"(d[2]), "+f"(d[3])
                 : "r"(a[0]), "r"(a[1]), "r"(a[2]), "r"(a[3]), "r"(b0), "r"(b1));
}

// Edge accessors robust to int32/int64 edge_index.
__device__ __forceinline__ int edge_at(const void* ei, size_t idx) {
    if (g_is64) return (int)((const long long*)ei)[idx];
    return ((const int*)ei)[idx];
}

// ---------------- dtype detection -------------------------------------------------
__global__ void k_detect(const int* __restrict__ w) {
    __shared__ int sh[256];
    int t = threadIdx.x;
    int nz = 0;
    for (int i = t; i < 2048; i += 256) nz |= w[2 * i + 1];
    sh[t] = nz;
    __syncthreads();
    for (int off = 128; off; off >>= 1) {
        if (t < off) sh[t] |= sh[t + off];
        __syncthreads();
    }
    if (t == 0) g_is64 = (sh[0] == 0) ? 1 : 0;
}

// ---------------- weight pre-conversion (fp32 -> bf16 hi/lo, once per launch) ------
__global__ void k_wconv(
    const float* p0, const float* p1, const float* p2, const float* p3,
    const float* p4, const float* p5, const float* p6, const float* p7,
    const float* p8, const float* p9, const float* p10, const float* p11) {
    int layer = blockIdx.y;
    const float *W1, *W2;
    int K1, K2, OUT;
    switch (layer) {
        case 0: W1 = p0;  W2 = p1;  K1 = 64;  K2 = 64;  OUT = 128; break;
        case 1: W1 = p2;  W2 = p3;  K1 = 128; K2 = 128; OUT = 128; break;
        case 2: W1 = p4;  W2 = p5;  K1 = 128; K2 = 128; OUT = 128; break;
        case 3: W1 = nullptr; W2 = p6; K1 = 0; K2 = 128; OUT = 64; break;
        case 4: W1 = nullptr; W2 = p7; K1 = 0; K2 = 64;  OUT = 128; break;
        case 5: W1 = p8;  W2 = p9;  K1 = 128; K2 = 128; OUT = 128; break;
        default: W1 = p10; W2 = p11; K1 = 128; K2 = 128; OUT = 64; break;
    }
    int KT = K1 + K2;
    int i = blockIdx.x * 256 + threadIdx.x;
    if (i >= OUT * KT) return;
    int o = i / KT, k = i % KT;
    float v = (K1 > 0 && k < K1) ? W1[o * K1 + k] : W2[o * K2 + (k - K1)];
    __nv_bfloat16 h = __float2bfloat16(v);
    float lo = v - __bfloat162float(h);
    g_wh[layer * 32768 + i] = h;
    g_wl[layer * 32768 + i] = __float2bfloat16(lo);
}

// ---------------- CSR build -------------------------------------------------------
__global__ void k_zero_cnt(int n) {
    int i = blockIdx.x * blockDim.x + threadIdx.x;
    if (i < n) g_cnt[i] = 0;
}
__global__ void k_count(const void* __restrict__ ei, int e) {
    int i = blockIdx.x * blockDim.x + threadIdx.x;
    if (i < e) {
        int d = edge_at(ei, (size_t)e + i);
        if ((unsigned)d < (unsigned)NN) atomicAdd(&g_cnt[d], 1);
    }
}
__global__ void k_scan1(int n) {
    __shared__ int sh[256];
    int t = threadIdx.x;
    int base = blockIdx.x * 2048 + t * 8;
    int v[8];
    int s = 0;
#pragma unroll
    for (int r = 0; r < 8; r++) {
        int idx = base + r;
        int c = (idx < n) ? g_cnt[idx] : 0;
        v[r] = s;
        s += c;
    }
    sh[t] = s;
    __syncthreads();
#pragma unroll
    for (int off = 1; off < 256; off <<= 1) {
        int tv = (t >= off) ? sh[t - off] : 0;
        __syncthreads();
        sh[t] += tv;
        __syncthreads();
    }
    if (t == 255) g_bsums[blockIdx.x] = sh[255];
    int excl = t ? sh[t - 1] : 0;
#pragma unroll
    for (int r = 0; r < 8; r++) {
        int idx = base + r;
        if (idx < n) g_rowptr[idx] = excl + v[r];
    }
}
__global__ void k_scan2(int nb) {
    __shared__ int sh[256];
    int t = threadIdx.x;
    int v = (t < nb) ? g_bsums[t] : 0;
    sh[t] = v;
    __syncthreads();
#pragma unroll
    for (int off = 1; off < 256; off <<= 1) {
        int tv = (t >= off) ? sh[t - off] : 0;
        __syncthreads();
        sh[t] += tv;
        __syncthreads();
    }
    if (t < nb) g_bsums[t] = t ? sh[t - 1] : 0;
}
__global__ void k_scan3(int n, int e) {
    int i = blockIdx.x * blockDim.x + threadIdx.x;
    if (i < n) {
        int r = g_rowptr[i] + g_bsums[i >> 11];
        g_rowptr[i] = r;
        g_cursor[i] = r;
        int c = g_cnt[i];
        g_inv[i] = 1.0f / (float)(c > 1 ? c : 1);
    }
    if (i == 0) g_rowptr[n] = e;
}
__global__ void k_scatter(const void* __restrict__ ei, int e) {
    int i = blockIdx.x * blockDim.x + threadIdx.x;
    if (i < e) {
        int d = edge_at(ei, (size_t)e + i);
        int s = edge_at(ei, (size_t)i);
        if ((unsigned)d < (unsigned)NN && (unsigned)s < (unsigned)NN) {
            int p = atomicAdd(&g_cursor[d], 1);
            g_csr[p] = s;
        }
    }
}

// ---------------- mean aggregation over CSR ---------------------------------------
template <int D>
__global__ void k_agg(const float* Xp, int sX, float* outp, int sO, int n) {
    const float* __restrict__ X = pickc(Xp, sX);
    float* __restrict__ out = pickm(outp, sO);
    constexpr int LPN = D / 4;
    int gid = blockIdx.x * blockDim.x + threadIdx.x;
    int node = gid / LPN;
    int lane = gid % LPN;
    if (node >= n) return;
    int beg = g_rowptr[node];
    int end = g_rowptr[node + 1];
    float4 acc = make_float4(0.f, 0.f, 0.f, 0.f);
    int e = beg;
    for (; e + 1 < end; e += 2) {
        int s0 = g_csr[e];
        int s1 = g_csr[e + 1];
        float4 a = *(const float4*)(X + (size_t)s0 * D + lane * 4);
        float4 b = *(const float4*)(X + (size_t)s1 * D + lane * 4);
        acc.x += a.x + b.x;
        acc.y += a.y + b.y;
        acc.z += a.z + b.z;
        acc.w += a.w + b.w;
    }
    if (e < end) {
        int s0 = g_csr[e];
        float4 a = *(const float4*)(X + (size_t)s0 * D + lane * 4);
        acc.x += a.x;
        acc.y += a.y;
        acc.z += a.z;
        acc.w += a.w;
    }
    float ic = g_inv[node];
    float4 o = make_float4(acc.x * ic, acc.y * ic, acc.z * ic, acc.w * ic);
    *(float4*)(out + (size_t)node * D + lane * 4) = o;
}

// ---------------- mma.sync SAGE GEMM: C = act([W1|W2] . [A1;A2] + b) ---------------
// bf16 hi/lo split (3 HMMA terms, fp32 accum). W tiles come pre-converted from
// g_wh/g_wl (pure copies); A converted in-kernel via truncation split:
// hi = bits&0xFFFF0000 (PRMT-packed), lo = v - hi (exact), bf16-rounded.
template <int K1, int K2, int OUT, int ACT, bool DUP>
__global__ void __launch_bounds__(256) k_gemm_mma(
    const float* A1p, int sA1, const float* A2p, int sA2,
    int layer, const float* __restrict__ bias,
    float* Cp, int sC, float* C2p, int n) {
    const float* __restrict__ A1 = pickc(A1p, sA1);
    const float* __restrict__ A2 = pickc(A2p, sA2);
    float* __restrict__ C = pickm(Cp, sC);
    float* __restrict__ C2 = C2p;

    constexpr int KT = K1 + K2;
    constexpr int NT = OUT / 8;       // 16 or 8 n-tiles per warp
    constexpr int STR = 40;           // bf16 row stride (80 bytes)

    __shared__ __align__(16) __nv_bfloat16 Ah[128 * STR];
    __shared__ __align__(16) __nv_bfloat16 Al[128 * STR];
    __shared__ __align__(16) __nv_bfloat16 Wh[OUT * STR];
    __shared__ __align__(16) __nv_bfloat16 Wl[OUT * STR];

    int tid = threadIdx.x;
    int w = tid >> 5;
    int lane = tid & 31;
    int row0 = blockIdx.x * 128;
    int lrow = tid >> 1, half = tid & 1;

    const __nv_bfloat16* __restrict__ gwh = g_wh + layer * 32768;
    const __nv_bfloat16* __restrict__ gwl = g_wl + layer * 32768;

    float acc[NT][4];
#pragma unroll
    for (int j = 0; j < NT; j++) {
        acc[j][0] = acc[j][1] = acc[j][2] = acc[j][3] = 0.f;
    }

    uint32_t bAh = smem_u32(Ah), bAl = smem_u32(Al);
    uint32_t bWh = smem_u32(Wh), bWl = smem_u32(Wl);

    // ldmatrix lane->address components (constant across chunks)
    uint32_t aoff = (uint32_t)(w * 16 + (lane & 7) + (lane & 8)) * 80 + ((lane & 16) ? 16u : 0u);
    uint32_t boff = (uint32_t)(lane & 7) * 80 + ((lane & 8) ? 16u : 0u);

#pragma unroll 1
    for (int k0 = 0; k0 < KT; k0 += 32) {
        const float* A;
        int lda, col0;
        if (K1 > 0 && k0 < K1) { A = A1; lda = K1; col0 = k0; }
        else                   { A = A2; lda = K2; col0 = k0 - K1; }

        // A tile: 128 rows x 32 cols; thread -> (row = tid/2, 16 cols = tid%2 half)
        {
            int r = row0 + lrow;
            bool val = r < n;
            const float4* src = (const float4*)(A + (size_t)r * lda + col0 + half * 16);
            char* dh = (char*)Ah + lrow * 80 + half * 32;
            char* dl = (char*)Al + lrow * 80 + half * 32;
#pragma unroll
            for (int q = 0; q < 4; q++) {
                float4 v = val ? src[q] : make_float4(0.f, 0.f, 0.f, 0.f);
                uint32_t ax = __float_as_uint(v.x), ay = __float_as_uint(v.y);
                uint32_t az = __float_as_uint(v.z), aw = __float_as_uint(v.w);
                uint32_t h0 = __byte_perm(ax, ay, 0x7632);
                uint32_t h1 = __byte_perm(az, aw, 0x7632);
                float lx = v.x - __uint_as_float(ax & 0xFFFF0000u);
                float ly = v.y - __uint_as_float(ay & 0xFFFF0000u);
                float lz = v.z - __uint_as_float(az & 0xFFFF0000u);
                float lw = v.w - __uint_as_float(aw & 0xFFFF0000u);
                uint32_t l0 = pack_bf2(lx, ly);
                uint32_t l1 = pack_bf2(lz, lw);
                *(uint2*)(dh + q * 8) = make_uint2(h0, h1);
                *(uint2*)(dl + q * 8) = make_uint2(l0, l1);
            }
        }
        // W tile: OUT rows x 32 cols — pure bf16 copy from pre-converted slabs
        if (lrow < OUT) {
            size_t gi = (size_t)lrow * KT + k0 + half * 16;
            const uint4* sh4 = (const uint4*)(gwh + gi);
            const uint4* sl4 = (const uint4*)(gwl + gi);
            uint4* dh4 = (uint4*)((char*)Wh + lrow * 80 + half * 32);
            uint4* dl4 = (uint4*)((char*)Wl + lrow * 80 + half * 32);
            dh4[0] = sh4[0];
            dh4[1] = sh4[1];
            dl4[0] = sl4[0];
            dl4[1] = sl4[1];
        }
        __syncthreads();

#pragma unroll
        for (int ks = 0; ks < 2; ks++) {
            uint32_t ah[4], al[4];
            ldsm4(bAh + aoff + ks * 32, ah);
            ldsm4(bAl + aoff + ks * 32, al);
#pragma unroll
            for (int j = 0; j < NT; j++) {
                uint32_t ba = (uint32_t)(j * 8) * 80 + boff + ks * 32;
                uint32_t bh0, bh1, bl0, bl1;
                ldsm2(bWh + ba, bh0, bh1);
                ldsm2(bWl + ba, bl0, bl1);
                mmabf(acc[j], ah, bh0, bh1);
                mmabf(acc[j], ah, bl0, bl1);
                mmabf(acc[j], al, bh0, bh1);
            }
        }
        __syncthreads();
    }

    // epilogue: D fragment (r0 = g, r1 = g+8; cols 2*t4, 2*t4+1 per n-tile)
    int g = lane >> 2, t4 = lane & 3;
    int r0 = row0 + w * 16 + g, r1 = r0 + 8;
#pragma unroll
    for (int j = 0; j < NT; j++) {
        int c = j * 8 + t4 * 2;
        float b0 = bias[c], b1 = bias[c + 1];
        float v00 = acc[j][0] + b0, v01 = acc[j][1] + b1;
        float v10 = acc[j][2] + b0, v11 = acc[j][3] + b1;
        if (ACT == 1) {
            v00 = tanhf(v00); v01 = tanhf(v01); v10 = tanhf(v10); v11 = tanhf(v11);
        } else if (ACT == 2) {
            v00 = v00 > 0.f ? v00 : 0.01f * v00;
            v01 = v01 > 0.f ? v01 : 0.01f * v01;
            v10 = v10 > 0.f ? v10 : 0.01f * v10;
            v11 = v11 > 0.f ? v11 : 0.01f * v11;
        }
        if (r0 < n) {
            *(float2*)(C + (size_t)r0 * OUT + c) = make_float2(v00, v01);
            if (DUP) *(float2*)(C2 + (size_t)r0 * OUT + c) = make_float2(v00, v01);
        }
        if (r1 < n) {
            *(float2*)(C + (size_t)r1 * OUT + c) = make_float2(v10, v11);
            if (DUP) *(float2*)(C2 + (size_t)r1 * OUT + c) = make_float2(v10, v11);
        }
    }
}

// ---------------- dec4: OUT=3, warp per node --------------------------------------
__global__ void k_dec4(const float* Amp, int sAm, const float* Op, int sO,
                       const float* __restrict__ Wl, const float* __restrict__ Wr,
                       const float* __restrict__ b,
                       float* __restrict__ out_xy, float* __restrict__ out_z, int n) {
    const float* __restrict__ Am = pickc(Amp, sAm);
    const float* __restrict__ O = pickc(Op, sO);
    int w = (blockIdx.x * blockDim.x + threadIdx.x) >> 5;
    int lane = threadIdx.x & 31;
    if (w >= n) return;
    const float* m = Am + (size_t)w * 64;
    const float* o = O + (size_t)w * 64;
    float m0 = m[lane], m1 = m[lane + 32];
    float o0 = o[lane], o1 = o[lane + 32];
    float r[3];
#pragma unroll
    for (int c = 0; c < 3; c++) {
        float v = Wl[c * 64 + lane] * m0 + Wl[c * 64 + lane + 32] * m1 +
                  Wr[c * 64 + lane] * o0 + Wr[c * 64 + lane + 32] * o1;
#pragma unroll
        for (int s = 16; s; s >>= 1) v += __shfl_down_sync(0xffffffffu, v, s);
        r[c] = v;
    }
    if (lane == 0) {
        out_xy[(size_t)w * 2 + 0] = r[0] + b[0];
        out_xy[(size_t)w * 2 + 1] = r[1] + b[1];
        out_z[w] = r[2] + b[2];
    }
}

// ---------------- host ------------------------------------------------------------
extern "C" void kernel_launch(void* const* d_in, const int* in_sizes, int n_in,
                              void* d_out, int out_size) {
    const float* x = (const float*)d_in[0];
    const void* ei = d_in[1];
    int N = in_sizes[0] / 64;
    int E = in_sizes[1] / 2;

    const float* g1Wl = (const float*)d_in[2];
    const float* g1b  = (const float*)d_in[3];
    const float* g1Wr = (const float*)d_in[4];
    const float* g2Wl = (const float*)d_in[5];
    const float* g2b  = (const float*)d_in[6];
    const float* g2Wr = (const float*)d_in[7];
    const float* g3Wl = (const float*)d_in[8];
    const float* g3b  = (const float*)d_in[9];
    const float* g3Wr = (const float*)d_in[10];
    const float* t2W  = (const float*)d_in[11];
    const float* t2b  = (const float*)d_in[12];
    const float* d1W  = (const float*)d_in[13];
    const float* d1b  = (const float*)d_in[14];
    const float* d2Wl = (const float*)d_in[15];
    const float* d2b  = (const float*)d_in[16];
    const float* d2Wr = (const float*)d_in[17];
    const float* d3Wl = (const float*)d_in[18];
    const float* d3b  = (const float*)d_in[19];
    const float* d3Wr = (const float*)d_in[20];
    const float* d4Wl = (const float*)d_in[21];
    const float* d4b  = (const float*)d_in[22];
    const float* d4Wr = (const float*)d_in[23];

    float* out = (float*)d_out;
    float* out_xy = out;
    float* out_z = out + 2 * (size_t)N;
    float* mu = out + 3 * (size_t)N;
    float* logvar = mu + 64 * (size_t)N;

    // ---- weight pre-conversion (parallel to CSR build) ----
    {
        dim3 grid(128, 7);
        k_wconv<<<grid, 256>>>(g1Wl, g1Wr, g2Wl, g2Wr, g3Wl, g3Wr,
                               t2W, d1W, d2Wl, d2Wr, d3Wl, d3Wr);
    }

    // ---- edge dtype detection + CSR build ----
    k_detect<<<1, 256>>>((const int*)ei);
    k_zero_cnt<<<(N + 255) / 256, 256>>>(N);
    k_count<<<(E + 255) / 256, 256>>>(ei, E);
    int NB = (N + 2047) / 2048;
    k_scan1<<<NB, 256>>>(N);
    k_scan2<<<1, 256>>>(NB);
    k_scan3<<<(N + 255) / 256, 256>>>(N, E);
    k_scatter<<<(E + 255) / 256, 256>>>(ei, E);

    int GB = (N + 127) / 128;
    int GA64 = (N * 16 + 255) / 256;
    int GA128 = (N * 32 + 255) / 256;

    // Buffer selectors: 1=A, 2=B, 3=C (0 = use the pointer argument)
    // ---- encoder ----
    k_agg<64><<<GA64, 256>>>(x, 0, nullptr, 1, N);
    k_gemm_mma<64, 64, 128, 1, false><<<GB, 256>>>(nullptr, 1, x, 0, 0, g1b, nullptr, 2, nullptr, N);
    k_agg<128><<<GA128, 256>>>(nullptr, 2, nullptr, 3, N);
    k_gemm_mma<128, 128, 128, 1, false><<<GB, 256>>>(nullptr, 3, nullptr, 2, 1, g2b, nullptr, 1, nullptr, N);
    k_agg<128><<<GA128, 256>>>(nullptr, 1, nullptr, 3, N);
    k_gemm_mma<128, 128, 128, 1, false><<<GB, 256>>>(nullptr, 3, nullptr, 1, 2, g3b, nullptr, 2, nullptr, N);
    // mu = h3 @ tr2_W.T + b ; logvar = mu
    k_gemm_mma<0, 128, 64, 0, true><<<GB, 256>>>(nullptr, 0, nullptr, 2, 3, t2b, mu, 0, logvar, N);

    // ---- decoder ----
    k_gemm_mma<0, 64, 128, 2, false><<<GB, 256>>>(nullptr, 0, mu, 0, 4, d1b, nullptr, 1, nullptr, N);
    k_agg<128><<<GA128, 256>>>(nullptr, 1, nullptr, 2, N);
    k_gemm_mma<128, 128, 128, 2, false><<<GB, 256>>>(nullptr, 2, nullptr, 1, 5, d2b, nullptr, 3, nullptr, N);
    k_agg<128><<<GA128, 256>>>(nullptr, 3, nullptr, 2, N);
    k_gemm_mma<128, 128, 64, 1, false><<<GB, 256>>>(nullptr, 2, nullptr, 3, 6, d3b, nullptr, 1, nullptr, N);
    k_agg<64><<<GA64, 256>>>(nullptr, 1, nullptr, 2, N);
    k_dec4<<<(N * 32 + 255) / 256, 256>>>(nullptr, 2, nullptr, 1, d4Wl, d4Wr, d4b, out_xy, out_z, N);
}

// round 17
// speedup vs baseline: 1.6999x; 1.0400x over previous
#include <cuda_runtime.h>
#include <cuda_bf16.h>
#include <cstdint>

#define NN 100000
#define EE 1600000

// ---------------- scratch (device globals: the sanctioned no-alloc workaround) ----
__device__ __align__(256) float g_bufA[(size_t)NN * 128];
__device__ __align__(256) float g_bufB[(size_t)NN * 128];
__device__ __align__(256) float g_bufC[(size_t)NN * 128];
__device__ int   g_cnt[NN];
__device__ int   g_rowptr[NN + 1];
__device__ int   g_cursor[NN];
__device__ int   g_bsums[256];
__device__ int   g_csr[EE];
__device__ float g_inv[NN];
__device__ int   g_is64;

// Pre-converted weights: 7 layers, slab stride 32768 (max OUT*KT = 128*256).
__device__ __align__(256) __nv_bfloat16 g_wh[7 * 32768];
__device__ __align__(256) __nv_bfloat16 g_wl[7 * 32768];

__device__ __forceinline__ const float* pickc(const float* p, int sel) {
    if (sel == 1) return g_bufA;
    if (sel == 2) return g_bufB;
    if (sel == 3) return g_bufC;
    return p;
}
__device__ __forceinline__ float* pickm(float* p, int sel) {
    if (sel == 1) return g_bufA;
    if (sel == 2) return g_bufB;
    if (sel == 3) return g_bufC;
    return p;
}

// ---------------- helpers ----------------------------------------------------------
__device__ __forceinline__ uint32_t smem_u32(const void* p) {
    uint32_t a;
    asm("{ .reg .u64 t; cvta.to.shared.u64 t, %1; cvt.u32.u64 %0, t; }" : "=r"(a) : "l"(p));
    return a;
}
__device__ __forceinline__ uint32_t pack_bf2(float a, float b) {
    uint32_t r;  // r = bf16(b)<<16 | bf16(a)
    asm("cvt.rn.bf16x2.f32 %0, %1, %2;" : "=r"(r) : "f"(b), "f"(a));
    return r;
}
__device__ __forceinline__ void ldsm4(uint32_t a, uint32_t* r) {
    asm volatile("ldmatrix.sync.aligned.m8n8.x4.shared.b16 {%0,%1,%2,%3}, [%4];"
                 : "=r"(r[0]), "=r"(r[1]), "=r"(r[2]), "=r"(r[3]) : "r"(a));
}
__device__ __forceinline__ void mmabf(float* d, const uint32_t* a, uint32_t b0, uint32_t b1) {
    asm volatile("mma.sync.aligned.m16n8k16.row.col.f32.bf16.bf16.f32 "
                 "{%0,%1,%2,%3}, {%4,%5,%6,%7}, {%8,%9}, {%0,%1,%2,%3};"
                 : "+f"(d[0]), "+f"(d[1]), "+f"(d[2]), "+f"(d[3])
                 : "r"(a[0]), "r"(a[1]), "r"(a[2]), "r"(a[3]), "r"(b0), "r"(b1));
}

// Edge accessors robust to int32/int64 edge_index.
__device__ __forceinline__ int edge_at(const void* ei, size_t idx) {
    if (g_is64) return (int)((const long long*)ei)[idx];
    return ((const int*)ei)[idx];
}

// ---------------- dtype detection -------------------------------------------------
__global__ void k_detect(const int* __restrict__ w) {
    __shared__ int sh[256];
    int t = threadIdx.x;
    int nz = 0;
    for (int i = t; i < 2048; i += 256) nz |= w[2 * i + 1];
    sh[t] = nz;
    __syncthreads();
    for (int off = 128; off; off >>= 1) {
        if (t < off) sh[t] |= sh[t + off];
        __syncthreads();
    }
    if (t == 0) g_is64 = (sh[0] == 0) ? 1 : 0;
}

// ---------------- weight pre-conversion (fp32 -> bf16 hi/lo, once per launch) ------
__global__ void k_wconv(
    const float* p0, const float* p1, const float* p2, const float* p3,
    const float* p4, const float* p5, const float* p6, const float* p7,
    const float* p8, const float* p9, const float* p10, const float* p11) {
    int layer = blockIdx.y;
    const float *W1, *W2;
    int K1, K2, OUT;
    switch (layer) {
        case 0: W1 = p0;  W2 = p1;  K1 = 64;  K2 = 64;  OUT = 128; break;
        case 1: W1 = p2;  W2 = p3;  K1 = 128; K2 = 128; OUT = 128; break;
        case 2: W1 = p4;  W2 = p5;  K1 = 128; K2 = 128; OUT = 128; break;
        case 3: W1 = nullptr; W2 = p6; K1 = 0; K2 = 128; OUT = 64; break;
        case 4: W1 = nullptr; W2 = p7; K1 = 0; K2 = 64;  OUT = 128; break;
        case 5: W1 = p8;  W2 = p9;  K1 = 128; K2 = 128; OUT = 128; break;
        default: W1 = p10; W2 = p11; K1 = 128; K2 = 128; OUT = 64; break;
    }
    int KT = K1 + K2;
    int i = blockIdx.x * 256 + threadIdx.x;
    if (i >= OUT * KT) return;
    int o = i / KT, k = i % KT;
    float v = (K1 > 0 && k < K1) ? W1[o * K1 + k] : W2[o * K2 + (k - K1)];
    __nv_bfloat16 h = __float2bfloat16(v);
    float lo = v - __bfloat162float(h);
    g_wh[layer * 32768 + i] = h;
    g_wl[layer * 32768 + i] = __float2bfloat16(lo);
}

// ---------------- CSR build -------------------------------------------------------
__global__ void k_zero_cnt(int n) {
    int i = blockIdx.x * blockDim.x + threadIdx.x;
    if (i < n) g_cnt[i] = 0;
}
__global__ void k_count(const void* __restrict__ ei, int e) {
    int i = blockIdx.x * blockDim.x + threadIdx.x;
    if (i < e) {
        int d = edge_at(ei, (size_t)e + i);
        if ((unsigned)d < (unsigned)NN) atomicAdd(&g_cnt[d], 1);
    }
}
__global__ void k_scan1(int n) {
    __shared__ int sh[256];
    int t = threadIdx.x;
    int base = blockIdx.x * 2048 + t * 8;
    int v[8];
    int s = 0;
#pragma unroll
    for (int r = 0; r < 8; r++) {
        int idx = base + r;
        int c = (idx < n) ? g_cnt[idx] : 0;
        v[r] = s;
        s += c;
    }
    sh[t] = s;
    __syncthreads();
#pragma unroll
    for (int off = 1; off < 256; off <<= 1) {
        int tv = (t >= off) ? sh[t - off] : 0;
        __syncthreads();
        sh[t] += tv;
        __syncthreads();
    }
    if (t == 255) g_bsums[blockIdx.x] = sh[255];
    int excl = t ? sh[t - 1] : 0;
#pragma unroll
    for (int r = 0; r < 8; r++) {
        int idx = base + r;
        if (idx < n) g_rowptr[idx] = excl + v[r];
    }
}
__global__ void k_scan2(int nb) {
    __shared__ int sh[256];
    int t = threadIdx.x;
    int v = (t < nb) ? g_bsums[t] : 0;
    sh[t] = v;
    __syncthreads();
#pragma unroll
    for (int off = 1; off < 256; off <<= 1) {
        int tv = (t >= off) ? sh[t - off] : 0;
        __syncthreads();
        sh[t] += tv;
        __syncthreads();
    }
    if (t < nb) g_bsums[t] = t ? sh[t - 1] : 0;
}
__global__ void k_scan3(int n, int e) {
    int i = blockIdx.x * blockDim.x + threadIdx.x;
    if (i < n) {
        int r = g_rowptr[i] + g_bsums[i >> 11];
        g_rowptr[i] = r;
        g_cursor[i] = r;
        int c = g_cnt[i];
        g_inv[i] = 1.0f / (float)(c > 1 ? c : 1);
    }
    if (i == 0) g_rowptr[n] = e;
}
__global__ void k_scatter(const void* __restrict__ ei, int e) {
    int i = blockIdx.x * blockDim.x + threadIdx.x;
    if (i < e) {
        int d = edge_at(ei, (size_t)e + i);
        int s = edge_at(ei, (size_t)i);
        if ((unsigned)d < (unsigned)NN && (unsigned)s < (unsigned)NN) {
            int p = atomicAdd(&g_cursor[d], 1);
            g_csr[p] = s;
        }
    }
}

// ---------------- mean aggregation over CSR ---------------------------------------
template <int D>
__global__ void k_agg(const float* Xp, int sX, float* outp, int sO, int n) {
    const float* __restrict__ X = pickc(Xp, sX);
    float* __restrict__ out = pickm(outp, sO);
    constexpr int LPN = D / 4;
    int gid = blockIdx.x * blockDim.x + threadIdx.x;
    int node = gid / LPN;
    int lane = gid % LPN;
    if (node >= n) return;
    int beg = g_rowptr[node];
    int end = g_rowptr[node + 1];
    float4 acc = make_float4(0.f, 0.f, 0.f, 0.f);
    int e = beg;
    for (; e + 1 < end; e += 2) {
        int s0 = g_csr[e];
        int s1 = g_csr[e + 1];
        float4 a = *(const float4*)(X + (size_t)s0 * D + lane * 4);
        float4 b = *(const float4*)(X + (size_t)s1 * D + lane * 4);
        acc.x += a.x + b.x;
        acc.y += a.y + b.y;
        acc.z += a.z + b.z;
        acc.w += a.w + b.w;
    }
    if (e < end) {
        int s0 = g_csr[e];
        float4 a = *(const float4*)(X + (size_t)s0 * D + lane * 4);
        acc.x += a.x;
        acc.y += a.y;
        acc.z += a.z;
        acc.w += a.w;
    }
    float ic = g_inv[node];
    float4 o = make_float4(acc.x * ic, acc.y * ic, acc.z * ic, acc.w * ic);
    *(float4*)(out + (size_t)node * D + lane * 4) = o;
}

// ---------------- pipelined mma.sync SAGE GEMM -------------------------------------
// C = act([W1|W2].[A1;A2] + b). bf16 hi/lo split (3 HMMA terms, fp32 accum).
// Double-buffered smem: prefetch chunk c+1 (A regs + W regs) before the MMA phase
// on chunk c, convert/store after, ONE __syncthreads per chunk. W b-fragments via
// ldmatrix.x4 covering two n-tiles.
template <int K1, int K2, int OUT, int ACT, bool DUP>
__global__ void __launch_bounds__(256, 2) k_gemm_mma(
    const float* A1p, int sA1, const float* A2p, int sA2,
    int layer, const float* __restrict__ bias,
    float* Cp, int sC, float* C2p, int n) {
    extern __shared__ char smem[];
    const float* __restrict__ A1 = pickc(A1p, sA1);
    const float* __restrict__ A2 = pickc(A2p, sA2);
    float* __restrict__ C = pickm(Cp, sC);
    float* __restrict__ C2 = C2p;

    constexpr int KT = K1 + K2;
    constexpr int NCH = KT / 32;
    constexpr int NT = OUT / 8;          // 16 or 8 n-tiles per warp
    constexpr int ABYTES = 128 * 80;     // A plane: 128 rows x 80B
    constexpr int WT = OUT * 80;         // W plane bytes
    constexpr int BUFS = 2 * ABYTES + 2 * WT;
    constexpr int OFF_AH = 0, OFF_AL = ABYTES, OFF_WH = 2 * ABYTES, OFF_WL = 2 * ABYTES + WT;

    int tid = threadIdx.x;
    int w = tid >> 5;
    int lane = tid & 31;
    int row0 = blockIdx.x * 128;
    int lrow = tid >> 1, half = tid & 1;

    const __nv_bfloat16* __restrict__ gwh = g_wh + layer * 32768;
    const __nv_bfloat16* __restrict__ gwl = g_wl + layer * 32768;

    float acc[NT][4];
#pragma unroll
    for (int j = 0; j < NT; j++) {
        acc[j][0] = acc[j][1] = acc[j][2] = acc[j][3] = 0.f;
    }

    uint32_t sbase = smem_u32(smem);
    // ldmatrix lane->address components (constant across chunks)
    uint32_t aoff = (uint32_t)(w * 16 + (lane & 7) + (lane & 8)) * 80 + ((lane & 16) ? 16u : 0u);
    uint32_t boff4 = (uint32_t)((lane >> 4) * 8 + (lane & 7)) * 80 + ((lane & 8) ? 16u : 0u);

    int r = row0 + lrow;
    bool aval = r < n;

    // ---- load chunk c into regs ----
    float4 ap[4];
    uint4 whp[2], wlp[2];
    auto load_chunk = [&](int c) {
        const float* A;
        int lda, col0;
        if (K1 > 0 && c * 32 < K1) { A = A1; lda = K1; col0 = c * 32; }
        else                        { A = A2; lda = K2; col0 = c * 32 - K1; }
        const float4* src = (const float4*)(A + (size_t)r * lda + col0 + half * 16);
#pragma unroll
        for (int q = 0; q < 4; q++)
            ap[q] = aval ? src[q] : make_float4(0.f, 0.f, 0.f, 0.f);
        if (lrow < OUT) {
            size_t gi = (size_t)lrow * KT + c * 32 + half * 16;
            const uint4* sh4 = (const uint4*)(gwh + gi);
            const uint4* sl4 = (const uint4*)(gwl + gi);
            whp[0] = sh4[0]; whp[1] = sh4[1];
            wlp[0] = sl4[0]; wlp[1] = sl4[1];
        }
    };
    // ---- convert regs and store into buffer b ----
    auto store_chunk = [&](int b) {
        char* base = smem + b * BUFS;
        char* dh = base + OFF_AH + lrow * 80 + half * 32;
        char* dl = base + OFF_AL + lrow * 80 + half * 32;
#pragma unroll
        for (int q = 0; q < 4; q++) {
            float4 v = ap[q];
            uint32_t ax = __float_as_uint(v.x), ay = __float_as_uint(v.y);
            uint32_t az = __float_as_uint(v.z), aw = __float_as_uint(v.w);
            uint32_t h0 = __byte_perm(ax, ay, 0x7632);
            uint32_t h1 = __byte_perm(az, aw, 0x7632);
            float lx = v.x - __uint_as_float(ax & 0xFFFF0000u);
            float ly = v.y - __uint_as_float(ay & 0xFFFF0000u);
            float lz = v.z - __uint_as_float(az & 0xFFFF0000u);
            float lw = v.w - __uint_as_float(aw & 0xFFFF0000u);
            *(uint2*)(dh + q * 8) = make_uint2(h0, h1);
            *(uint2*)(dl + q * 8) = make_uint2(pack_bf2(lx, ly), pack_bf2(lz, lw));
        }
        if (lrow < OUT) {
            uint4* dwh = (uint4*)(base + OFF_WH + lrow * 80 + half * 32);
            uint4* dwl = (uint4*)(base + OFF_WL + lrow * 80 + half * 32);
            dwh[0] = whp[0];
            *(uint4*)((char*)dwh + 16) = whp[1];
            dwl[0] = wlp[0];
            *(uint4*)((char*)dwl + 16) = wlp[1];
        }
    };

    load_chunk(0);
    store_chunk(0);
    __syncthreads();

#pragma unroll 1
    for (int c = 0; c < NCH; c++) {
        int b = c & 1;
        if (c + 1 < NCH) load_chunk(c + 1);   // LDGs in flight during MMA phase

        uint32_t sb = sbase + b * BUFS;
        uint32_t bAh = sb + OFF_AH, bAl = sb + OFF_AL;
        uint32_t bWh = sb + OFF_WH, bWl = sb + OFF_WL;
#pragma unroll
        for (int ks = 0; ks < 2; ks++) {
            uint32_t ah[4], al[4];
            ldsm4(bAh + aoff + ks * 32, ah);
            ldsm4(bAl + aoff + ks * 32, al);
#pragma unroll
            for (int j = 0; j < NT; j += 2) {
                uint32_t ba = (uint32_t)(j * 8) * 80 + boff4 + ks * 32;
                uint32_t bh[4], bl[4];
                ldsm4(bWh + ba, bh);
                ldsm4(bWl + ba, bl);
                mmabf(acc[j], ah, bh[0], bh[1]);
                mmabf(acc[j], ah, bl[0], bl[1]);
                mmabf(acc[j], al, bh[0], bh[1]);
                mmabf(acc[j + 1], ah, bh[2], bh[3]);
                mmabf(acc[j + 1], ah, bl[2], bl[3]);
                mmabf(acc[j + 1], al, bh[2], bh[3]);
            }
        }
        if (c + 1 < NCH) store_chunk(b ^ 1);
        __syncthreads();
    }

    // epilogue: D fragment (r0 = g, r1 = g+8; cols 2*t4, 2*t4+1 per n-tile)
    int g = lane >> 2, t4 = lane & 3;
    int r0 = row0 + w * 16 + g, r1 = r0 + 8;
#pragma unroll
    for (int j = 0; j < NT; j++) {
        int c = j * 8 + t4 * 2;
        float b0 = bias[c], b1 = bias[c + 1];
        float v00 = acc[j][0] + b0, v01 = acc[j][1] + b1;
        float v10 = acc[j][2] + b0, v11 = acc[j][3] + b1;
        if (ACT == 1) {
            v00 = tanhf(v00); v01 = tanhf(v01); v10 = tanhf(v10); v11 = tanhf(v11);
        } else if (ACT == 2) {
            v00 = v00 > 0.f ? v00 : 0.01f * v00;
            v01 = v01 > 0.f ? v01 : 0.01f * v01;
            v10 = v10 > 0.f ? v10 : 0.01f * v10;
            v11 = v11 > 0.f ? v11 : 0.01f * v11;
        }
        if (r0 < n) {
            *(float2*)(C + (size_t)r0 * OUT + c) = make_float2(v00, v01);
            if (DUP) *(float2*)(C2 + (size_t)r0 * OUT + c) = make_float2(v00, v01);
        }
        if (r1 < n) {
            *(float2*)(C + (size_t)r1 * OUT + c) = make_float2(v10, v11);
            if (DUP) *(float2*)(C2 + (size_t)r1 * OUT + c) = make_float2(v10, v11);
        }
    }
}

// ---------------- dec4: OUT=3, warp per node --------------------------------------
__global__ void k_dec4(const float* Amp, int sAm, const float* Op, int sO,
                       const float* __restrict__ Wl, const float* __restrict__ Wr,
                       const float* __restrict__ b,
                       float* __restrict__ out_xy, float* __restrict__ out_z, int n) {
    const float* __restrict__ Am = pickc(Amp, sAm);
    const float* __restrict__ O = pickc(Op, sO);
    int w = (blockIdx.x * blockDim.x + threadIdx.x) >> 5;
    int lane = threadIdx.x & 31;
    if (w >= n) return;
    const float* m = Am + (size_t)w * 64;
    const float* o = O + (size_t)w * 64;
    float m0 = m[lane], m1 = m[lane + 32];
    float o0 = o[lane], o1 = o[lane + 32];
    float r[3];
#pragma unroll
    for (int c = 0; c < 3; c++) {
        float v = Wl[c * 64 + lane] * m0 + Wl[c * 64 + lane + 32] * m1 +
                  Wr[c * 64 + lane] * o0 + Wr[c * 64 + lane + 32] * o1;
#pragma unroll
        for (int s = 16; s; s >>= 1) v += __shfl_down_sync(0xffffffffu, v, s);
        r[c] = v;
    }
    if (lane == 0) {
        out_xy[(size_t)w * 2 + 0] = r[0] + b[0];
        out_xy[(size_t)w * 2 + 1] = r[1] + b[1];
        out_z[w] = r[2] + b[2];
    }
}

// ---------------- host ------------------------------------------------------------
extern "C" void kernel_launch(void* const* d_in, const int* in_sizes, int n_in,
                              void* d_out, int out_size) {
    const float* x = (const float*)d_in[0];
    const void* ei = d_in[1];
    int N = in_sizes[0] / 64;
    int E = in_sizes[1] / 2;

    const float* g1Wl = (const float*)d_in[2];
    const float* g1b  = (const float*)d_in[3];
    const float* g1Wr = (const float*)d_in[4];
    const float* g2Wl = (const float*)d_in[5];
    const float* g2b  = (const float*)d_in[6];
    const float* g2Wr = (const float*)d_in[7];
    const float* g3Wl = (const float*)d_in[8];
    const float* g3b  = (const float*)d_in[9];
    const float* g3Wr = (const float*)d_in[10];
    const float* t2W  = (const float*)d_in[11];
    const float* t2b  = (const float*)d_in[12];
    const float* d1W  = (const float*)d_in[13];
    const float* d1b  = (const float*)d_in[14];
    const float* d2Wl = (const float*)d_in[15];
    const float* d2b  = (const float*)d_in[16];
    const float* d2Wr = (const float*)d_in[17];
    const float* d3Wl = (const float*)d_in[18];
    const float* d3b  = (const float*)d_in[19];
    const float* d3Wr = (const float*)d_in[20];
    const float* d4Wl = (const float*)d_in[21];
    const float* d4b  = (const float*)d_in[22];
    const float* d4Wr = (const float*)d_in[23];

    float* out = (float*)d_out;
    float* out_xy = out;
    float* out_z = out + 2 * (size_t)N;
    float* mu = out + 3 * (size_t)N;
    float* logvar = mu + 64 * (size_t)N;

    // Dynamic smem: 2 buffers x (2*A plane + 2*W plane)
    const int SM128 = 2 * (2 * 128 * 80 + 2 * 128 * 80);  // 81920
    const int SM64  = 2 * (2 * 128 * 80 + 2 * 64 * 80);   // 61440
    cudaFuncSetAttribute(k_gemm_mma<64, 64, 128, 1, false>,   cudaFuncAttributeMaxDynamicSharedMemorySize, SM128);
    cudaFuncSetAttribute(k_gemm_mma<128, 128, 128, 1, false>, cudaFuncAttributeMaxDynamicSharedMemorySize, SM128);
    cudaFuncSetAttribute(k_gemm_mma<0, 128, 64, 0, true>,     cudaFuncAttributeMaxDynamicSharedMemorySize, SM64);
    cudaFuncSetAttribute(k_gemm_mma<0, 64, 128, 2, false>,    cudaFuncAttributeMaxDynamicSharedMemorySize, SM128);
    cudaFuncSetAttribute(k_gemm_mma<128, 128, 128, 2, false>, cudaFuncAttributeMaxDynamicSharedMemorySize, SM128);
    cudaFuncSetAttribute(k_gemm_mma<128, 128, 64, 1, false>,  cudaFuncAttributeMaxDynamicSharedMemorySize, SM64);

    // ---- weight pre-conversion (parallel to CSR build) ----
    {
        dim3 grid(128, 7);
        k_wconv<<<grid, 256>>>(g1Wl, g1Wr, g2Wl, g2Wr, g3Wl, g3Wr,
                               t2W, d1W, d2Wl, d2Wr, d3Wl, d3Wr);
    }

    // ---- edge dtype detection + CSR build ----
    k_detect<<<1, 256>>>((const int*)ei);
    k_zero_cnt<<<(N + 255) / 256, 256>>>(N);
    k_count<<<(E + 255) / 256, 256>>>(ei, E);
    int NB = (N + 2047) / 2048;
    k_scan1<<<NB, 256>>>(N);
    k_scan2<<<1, 256>>>(NB);
    k_scan3<<<(N + 255) / 256, 256>>>(N, E);
    k_scatter<<<(E + 255) / 256, 256>>>(ei, E);

    int GB = (N + 127) / 128;
    int GA64 = (N * 16 + 255) / 256;
    int GA128 = (N * 32 + 255) / 256;

    // Buffer selectors: 1=A, 2=B, 3=C (0 = use the pointer argument)
    // ---- encoder ----
    k_agg<64><<<GA64, 256>>>(x, 0, nullptr, 1, N);
    k_gemm_mma<64, 64, 128, 1, false><<<GB, 256, SM128>>>(nullptr, 1, x, 0, 0, g1b, nullptr, 2, nullptr, N);
    k_agg<128><<<GA128, 256>>>(nullptr, 2, nullptr, 3, N);
    k_gemm_mma<128, 128, 128, 1, false><<<GB, 256, SM128>>>(nullptr, 3, nullptr, 2, 1, g2b, nullptr, 1, nullptr, N);
    k_agg<128><<<GA128, 256>>>(nullptr, 1, nullptr, 3, N);
    k_gemm_mma<128, 128, 128, 1, false><<<GB, 256, SM128>>>(nullptr, 3, nullptr, 1, 2, g3b, nullptr, 2, nullptr, N);
    // mu = h3 @ tr2_W.T + b ; logvar = mu
    k_gemm_mma<0, 128, 64, 0, true><<<GB, 256, SM64>>>(nullptr, 0, nullptr, 2, 3, t2b, mu, 0, logvar, N);

    // ---- decoder ----
    k_gemm_mma<0, 64, 128, 2, false><<<GB, 256, SM128>>>(nullptr, 0, mu, 0, 4, d1b, nullptr, 1, nullptr, N);
    k_agg<128><<<GA128, 256>>>(nullptr, 1, nullptr, 2, N);
    k_gemm_mma<128, 128, 128, 2, false><<<GB, 256, SM128>>>(nullptr, 2, nullptr, 1, 5, d2b, nullptr, 3, nullptr, N);
    k_agg<128><<<GA128, 256>>>(nullptr, 3, nullptr, 2, N);
    k_gemm_mma<128, 128, 64, 1, false><<<GB, 256, SM64>>>(nullptr, 2, nullptr, 3, 6, d3b, nullptr, 1, nullptr, N);
    k_agg<64><<<GA64, 256>>>(nullptr, 1, nullptr, 2, N);
    k_dec4<<<(N * 32 + 255) / 256, 256>>>(nullptr, 2, nullptr, 1, d4Wl, d4Wr, d4b, out_xy, out_z, N);
}